// round 12
// baseline (speedup 1.0000x reference)
#include <cuda_runtime.h>
#include <cuda_bf16.h>
#include <cstdint>

typedef unsigned long long u64;

#define B_  16
#define L_  1024
#define F_  512
#define H_  8
#define D_  64
#define U_  35
#define BH_ (B_*H_)
#define ML_ (B_*L_)
#define RMAX_ 384      // padded compacted rows per batch (3*128 >= 280 max)

#define INF_F __int_as_float(0x7f800000)

// -------- device scratch --------
__device__ float g_q[(size_t)BH_*L_*D_];
__device__ float g_k[(size_t)BH_*L_*D_];
__device__ float g_v[(size_t)BH_*L_*D_];
__device__ float g_M[(size_t)BH_*L_];
__device__ int   g_idx[BH_*U_];
__device__ float g_x2[(size_t)ML_*F_];
__device__ float g_sc[(size_t)BH_*U_*L_];
__device__ float g_vm[BH_*D_];
__device__ float g_om[B_*F_];
__device__ int   g_flag[B_*L_];
__device__ int   g_cnt[B_];
__device__ int   g_rows[B_*L_];
__device__ __nv_bfloat16 g_xcat[3ULL*ML_*1024];  // [hi(512)|lo(512)] per row
__device__ __nv_bfloat16 g_wcat[3ULL*F_*1024];
__device__ __nv_bfloat16 g_qs[(size_t)BH_*L_*128];  // q split [hi(64)|lo(64)]
__device__ __nv_bfloat16 g_ks[(size_t)BH_*L_*128];  // k split
__device__ __nv_bfloat16 g_x2s[(size_t)B_*RMAX_*1024]; // compacted x2 split
__device__ __nv_bfloat16 g_wo[(size_t)F_*1024];        // Wo split

// -------- f32x2 helpers --------
__device__ __forceinline__ void fma2(u64 &acc, u64 a, u64 b) {
    asm("fma.rn.f32x2 %0, %1, %2, %0;" : "+l"(acc) : "l"(a), "l"(b));
}
__device__ __forceinline__ u64 dup2(float v) {
    u64 r; asm("mov.b64 %0, {%1, %1};" : "=l"(r) : "f"(v)); return r;
}
__device__ __forceinline__ float2 unpk(u64 v) {
    float2 r; asm("mov.b64 {%0, %1}, %2;" : "=f"(r.x), "=f"(r.y) : "l"(v)); return r;
}

// -------- mma.sync helpers (baseline PTX, sm_80+) --------
__device__ __forceinline__ uint32_t smem_u32(const void* p) {
    uint32_t a;
    asm("{ .reg .u64 t; cvta.to.shared.u64 t, %1; cvt.u32.u64 %0, t; }" : "=r"(a) : "l"(p));
    return a;
}
#define LDSM4(r, addr) \
    asm volatile("ldmatrix.sync.aligned.m8n8.x4.shared.b16 {%0,%1,%2,%3}, [%4];" \
        : "=r"((r)[0]), "=r"((r)[1]), "=r"((r)[2]), "=r"((r)[3]) : "r"(addr))
#define MMA16816(c, a, b0v, b1v) \
    asm("mma.sync.aligned.m16n8k16.row.col.f32.bf16.bf16.f32 " \
        "{%0,%1,%2,%3}, {%4,%5,%6,%7}, {%8,%9}, {%0,%1,%2,%3};" \
        : "+f"((c)[0]), "+f"((c)[1]), "+f"((c)[2]), "+f"((c)[3]) \
        : "r"((a)[0]), "r"((a)[1]), "r"((a)[2]), "r"((a)[3]), "r"(b0v), "r"(b1v))

__device__ __forceinline__ uint32_t pack_bf2(float x, float y) {
    __nv_bfloat162 t;
    t.x = __float2bfloat16(x);
    t.y = __float2bfloat16(y);
    return *(uint32_t*)&t;
}

// term-major split MMA block (gap-4 chains)
#define MMA_GROUP(accA0, accA1, accB0, accB1, ah, al, bh, bl) do { \
    MMA16816(accA0, (ah)[0], (bh)[0], (bh)[2]); \
    MMA16816(accA1, (ah)[0], (bh)[1], (bh)[3]); \
    MMA16816(accB0, (ah)[1], (bh)[0], (bh)[2]); \
    MMA16816(accB1, (ah)[1], (bh)[1], (bh)[3]); \
    MMA16816(accA0, (ah)[0], (bl)[0], (bl)[2]); \
    MMA16816(accA1, (ah)[0], (bl)[1], (bl)[3]); \
    MMA16816(accB0, (ah)[1], (bl)[0], (bl)[2]); \
    MMA16816(accB1, (ah)[1], (bl)[1], (bl)[3]); \
    MMA16816(accA0, (al)[0], (bh)[0], (bh)[2]); \
    MMA16816(accA1, (al)[0], (bh)[1], (bh)[3]); \
    MMA16816(accB0, (al)[1], (bh)[0], (bh)[2]); \
    MMA16816(accB1, (al)[1], (bh)[1], (bh)[3]); \
} while (0)

// ============================================================
// fp32 -> bf16 hi/lo split  (X rows, W rows, Wo)
// ============================================================
__global__ __launch_bounds__(256)
void convx_kernel(const float* __restrict__ q, const float* __restrict__ k,
                  const float* __restrict__ v)
{
    const int z = blockIdx.y;
    const float* src = (z == 0) ? q : (z == 1) ? k : v;
    __nv_bfloat16* dst = g_xcat + (size_t)z * ((size_t)ML_*1024);
    size_t e = ((size_t)blockIdx.x*256 + threadIdx.x) * 4;
    float4 x = *(const float4*)(src + e);
    size_t m = e >> 9, kk = e & 511;
    float xv[4] = {x.x, x.y, x.z, x.w};
    __nv_bfloat16 hi[4], lo[4];
#pragma unroll
    for (int i = 0; i < 4; i++) {
        hi[i] = __float2bfloat16(xv[i]);
        lo[i] = __float2bfloat16(xv[i] - __bfloat162float(hi[i]));
    }
    *(uint2*)(dst + m*1024 + kk)       = *(uint2*)hi;
    *(uint2*)(dst + m*1024 + 512 + kk) = *(uint2*)lo;
}

__global__ __launch_bounds__(256)
void convw_kernel(const float* __restrict__ wq, const float* __restrict__ wk,
                  const float* __restrict__ wv, const float* __restrict__ wo)
{
    const int z = blockIdx.y;
    const float* src = (z == 0) ? wq : (z == 1) ? wk : (z == 2) ? wv : wo;
    __nv_bfloat16* dst = (z < 3) ? (g_wcat + (size_t)z * ((size_t)F_*1024)) : g_wo;
    size_t e = ((size_t)blockIdx.x*256 + threadIdx.x) * 4;
    float4 x = *(const float4*)(src + e);
    size_t m = e >> 9, kk = e & 511;
    float xv[4] = {x.x, x.y, x.z, x.w};
    __nv_bfloat16 hi[4], lo[4];
#pragma unroll
    for (int i = 0; i < 4; i++) {
        hi[i] = __float2bfloat16(xv[i]);
        lo[i] = __float2bfloat16(xv[i] - __bfloat162float(hi[i]));
    }
    *(uint2*)(dst + m*1024 + kk)       = *(uint2*)hi;
    *(uint2*)(dst + m*1024 + 512 + kk) = *(uint2*)lo;
}

// ============================================================
// HMMA projection GEMM: C = X @ W^T + b via bf16 split x3.
// CTA 128x128, 8 warps (4m x 2n), warp tile 32x64, k-chunk 64.
// z<2 epilogue also emits bf16 hi/lo split rows (g_qs/g_ks).
// ============================================================
#define TS 72
#define TILE_E (128*TS)

__global__ __launch_bounds__(256, 2)
void hmma_proj_kernel(float* qd, float* kd, float* vd,
                      const float* __restrict__ bq,
                      const float* __restrict__ bk,
                      const float* __restrict__ bv)
{
    __shared__ __align__(16) __nv_bfloat16 Ah[TILE_E];
    __shared__ __align__(16) __nv_bfloat16 Al[TILE_E];
    __shared__ __align__(16) __nv_bfloat16 Bh[TILE_E];
    __shared__ __align__(16) __nv_bfloat16 Bl[TILE_E];

    const int tid = threadIdx.x;
    const int lane = tid & 31, wid = tid >> 5;
    const int z = blockIdx.z;
    const int m0 = blockIdx.y * 128, n0 = blockIdx.x * 128;
    const int wm = (wid >> 1) * 32;
    const int wn = (wid & 1) * 64;

    const __nv_bfloat16* xc = g_xcat + (size_t)z * ((size_t)ML_*1024);
    const __nv_bfloat16* wc = g_wcat + (size_t)z * ((size_t)F_*1024);
    float* dst = (z == 0) ? qd : (z == 1) ? kd : vd;
    const float* bias = (z == 0) ? bq : (z == 1) ? bk : bv;

    float acc[2][8][4];
#pragma unroll
    for (int i = 0; i < 2; i++)
#pragma unroll
        for (int j = 0; j < 8; j++)
#pragma unroll
            for (int c = 0; c < 4; c++) acc[i][j][c] = 0.f;

    const int lrow = lane & 15, lhalf = lane >> 4;
    const uint32_t sAh = smem_u32(Ah), sAl = smem_u32(Al);
    const uint32_t sBh = smem_u32(Bh), sBl = smem_u32(Bl);
    uint32_t aoffH = sAh + (uint32_t)(((wm + lrow)*TS + lhalf*8) * 2);
    uint32_t aoffL = sAl + (uint32_t)(((wm + lrow)*TS + lhalf*8) * 2);
    uint32_t boffH[4], boffL[4];
#pragma unroll
    for (int nq = 0; nq < 4; nq++) {
        boffH[nq] = sBh + (uint32_t)(((wn + nq*16 + lrow)*TS + lhalf*8) * 2);
        boffL[nq] = sBl + (uint32_t)(((wn + nq*16 + lrow)*TS + lhalf*8) * 2);
    }

    for (int kc = 0; kc < 8; kc++) {
        __syncthreads();
#pragma unroll
        for (int it = 0; it < 4; it++) {
            int idx = tid + it*256;
            int row = idx >> 3, c8 = (idx & 7) << 3;
            const __nv_bfloat16* xr = xc + (size_t)(m0 + row)*1024 + kc*64 + c8;
            const __nv_bfloat16* wr = wc + (size_t)(n0 + row)*1024 + kc*64 + c8;
            *(uint4*)(Ah + row*TS + c8) = *(const uint4*)(xr);
            *(uint4*)(Al + row*TS + c8) = *(const uint4*)(xr + 512);
            *(uint4*)(Bh + row*TS + c8) = *(const uint4*)(wr);
            *(uint4*)(Bl + row*TS + c8) = *(const uint4*)(wr + 512);
        }
        __syncthreads();

#pragma unroll
        for (int kt = 0; kt < 4; kt++) {
            const uint32_t kb = kt * 32;
            uint32_t ah[2][4], al[2][4];
            LDSM4(ah[0], aoffH + kb);
            LDSM4(ah[1], aoffH + kb + 16*TS*2);
            LDSM4(al[0], aoffL + kb);
            LDSM4(al[1], aoffL + kb + 16*TS*2);
#pragma unroll
            for (int nq = 0; nq < 4; nq++) {
                uint32_t bh[4], bl[4];
                LDSM4(bh, boffH[nq] + kb);
                LDSM4(bl, boffL[nq] + kb);
                MMA_GROUP(acc[0][nq*2], acc[0][nq*2+1],
                          acc[1][nq*2], acc[1][nq*2+1],
                          ah, al, bh, bl);
            }
        }
    }

    // ---- epilogue: fp32 out + (z<2) bf16 hi/lo split out ----
    __nv_bfloat16* sp = (z == 0) ? g_qs : g_ks;
    const int r0 = lane >> 2, c0 = (lane & 3) << 1;
#pragma unroll
    for (int mi = 0; mi < 2; mi++) {
        int mA = m0 + wm + mi*16 + r0;
        int mB = mA + 8;
        int bA = mA >> 10, lA = mA & (L_-1);
        int bB = mB >> 10, lB = mB & (L_-1);
#pragma unroll
        for (int ni = 0; ni < 8; ni++) {
            int n = n0 + wn + ni*8 + c0;
            int h = n >> 6, d = n & 63;
            float b0v = bias[n], b1v = bias[n+1];
            float vA0 = acc[mi][ni][0] + b0v, vA1 = acc[mi][ni][1] + b1v;
            float vB0 = acc[mi][ni][2] + b0v, vB1 = acc[mi][ni][3] + b1v;
            size_t rowA = (size_t)(bA*H_ + h)*L_ + lA;
            size_t rowB = (size_t)(bB*H_ + h)*L_ + lB;
            *(float2*)(dst + rowA*D_ + d) = make_float2(vA0, vA1);
            *(float2*)(dst + rowB*D_ + d) = make_float2(vB0, vB1);
            if (z < 2) {
                float hA0 = __bfloat162float(__float2bfloat16(vA0));
                float hA1 = __bfloat162float(__float2bfloat16(vA1));
                float hB0 = __bfloat162float(__float2bfloat16(vB0));
                float hB1 = __bfloat162float(__float2bfloat16(vB1));
                __nv_bfloat16* pA = sp + rowA*128 + d;
                __nv_bfloat16* pB = sp + rowB*128 + d;
                *(uint32_t*)pA        = pack_bf2(vA0, vA1);
                *(uint32_t*)(pA + 64) = pack_bf2(vA0 - hA0, vA1 - hA1);
                *(uint32_t*)pB        = pack_bf2(vB0, vB1);
                *(uint32_t*)(pB + 64) = pack_bf2(vB0 - hB0, vB1 - hB1);
            }
        }
    }
}

// ============================================================
// qk M kernel via HMMA split-bf16 (static smem, 2 CTAs/SM)
// ============================================================
__global__ __launch_bounds__(256, 2)
void qk_hmma_kernel()
{
    __shared__ __align__(16) __nv_bfloat16 Qh[TILE_E];
    __shared__ __align__(16) __nv_bfloat16 Ql[TILE_E];
    __shared__ __align__(16) __nv_bfloat16 Kh[TILE_E];
    __shared__ __align__(16) __nv_bfloat16 Kl[TILE_E];
    __shared__ float redmax[2][128];
    __shared__ float redsum[2][128];

    const int tid = threadIdx.x;
    const int lane = tid & 31, wid = tid >> 5;
    const int bh_ = blockIdx.y, q0 = blockIdx.x * 128;
    const int wm = (wid >> 1) * 32, wn = (wid & 1) * 64;

    const __nv_bfloat16* qs = g_qs + (size_t)bh_*L_*128;
    const __nv_bfloat16* ks = g_ks + (size_t)bh_*L_*128;

#pragma unroll
    for (int it = 0; it < 4; it++) {
        int idx = tid + it*256;
        int row = idx >> 3, c8 = (idx & 7) << 3;
        const __nv_bfloat16* src = qs + (size_t)(q0 + row)*128 + c8;
        *(uint4*)(Qh + row*TS + c8) = *(const uint4*)(src);
        *(uint4*)(Ql + row*TS + c8) = *(const uint4*)(src + 64);
    }

    const int lrow = lane & 15, lhalf = lane >> 4;
    const uint32_t sQh = smem_u32(Qh), sQl = smem_u32(Ql);
    const uint32_t sKh = smem_u32(Kh), sKl = smem_u32(Kl);
    uint32_t aoffH = sQh + (uint32_t)(((wm + lrow)*TS + lhalf*8) * 2);
    uint32_t aoffL = sQl + (uint32_t)(((wm + lrow)*TS + lhalf*8) * 2);
    uint32_t boffH[4], boffL[4];
#pragma unroll
    for (int nq = 0; nq < 4; nq++) {
        boffH[nq] = sKh + (uint32_t)(((wn + nq*16 + lrow)*TS + lhalf*8) * 2);
        boffL[nq] = sKl + (uint32_t)(((wn + nq*16 + lrow)*TS + lhalf*8) * 2);
    }

    float rmax_[2][2], rsum_[2][2];
#pragma unroll
    for (int i = 0; i < 2; i++)
#pragma unroll
        for (int j = 0; j < 2; j++) { rmax_[i][j] = -INF_F; rsum_[i][j] = 0.f; }

    for (int kt = 0; kt < 8; kt++) {
        __syncthreads();
#pragma unroll
        for (int it = 0; it < 4; it++) {
            int idx = tid + it*256;
            int row = idx >> 3, c8 = (idx & 7) << 3;
            const __nv_bfloat16* src = ks + (size_t)(kt*128 + row)*128 + c8;
            *(uint4*)(Kh + row*TS + c8) = *(const uint4*)(src);
            *(uint4*)(Kl + row*TS + c8) = *(const uint4*)(src + 64);
        }
        __syncthreads();

        float acc[2][8][4];
#pragma unroll
        for (int i = 0; i < 2; i++)
#pragma unroll
            for (int j = 0; j < 8; j++)
#pragma unroll
                for (int c = 0; c < 4; c++) acc[i][j][c] = 0.f;

#pragma unroll
        for (int k16 = 0; k16 < 4; k16++) {
            const uint32_t kb = k16 * 32;
            uint32_t ah[2][4], al[2][4];
            LDSM4(ah[0], aoffH + kb);
            LDSM4(ah[1], aoffH + kb + 16*TS*2);
            LDSM4(al[0], aoffL + kb);
            LDSM4(al[1], aoffL + kb + 16*TS*2);
#pragma unroll
            for (int nq = 0; nq < 4; nq++) {
                uint32_t bhf[4], blf[4];
                LDSM4(bhf, boffH[nq] + kb);
                LDSM4(blf, boffL[nq] + kb);
                MMA_GROUP(acc[0][nq*2], acc[0][nq*2+1],
                          acc[1][nq*2], acc[1][nq*2+1],
                          ah, al, bhf, blf);
            }
        }

#pragma unroll
        for (int mi = 0; mi < 2; mi++) {
            float m0 = -INF_F, m1 = -INF_F, s0 = 0.f, s1 = 0.f;
#pragma unroll
            for (int ni = 0; ni < 8; ni++) {
                m0 = fmaxf(m0, fmaxf(acc[mi][ni][0], acc[mi][ni][1]));
                s0 += acc[mi][ni][0] + acc[mi][ni][1];
                m1 = fmaxf(m1, fmaxf(acc[mi][ni][2], acc[mi][ni][3]));
                s1 += acc[mi][ni][2] + acc[mi][ni][3];
            }
            rmax_[mi][0] = fmaxf(rmax_[mi][0], m0); rsum_[mi][0] += s0;
            rmax_[mi][1] = fmaxf(rmax_[mi][1], m1); rsum_[mi][1] += s1;
        }
    }

#pragma unroll
    for (int mi = 0; mi < 2; mi++)
#pragma unroll
        for (int hf = 0; hf < 2; hf++) {
            float m = rmax_[mi][hf], s = rsum_[mi][hf];
#pragma unroll
            for (int off = 1; off <= 2; off <<= 1) {
                m = fmaxf(m, __shfl_xor_sync(0xffffffffu, m, off));
                s += __shfl_xor_sync(0xffffffffu, s, off);
            }
            rmax_[mi][hf] = m; rsum_[mi][hf] = s;
        }
    if ((lane & 3) == 0) {
        int r0 = lane >> 2;
#pragma unroll
        for (int mi = 0; mi < 2; mi++)
#pragma unroll
            for (int hf = 0; hf < 2; hf++) {
                int row = wm + mi*16 + hf*8 + r0;
                redmax[wid & 1][row] = rmax_[mi][hf];
                redsum[wid & 1][row] = rsum_[mi][hf];
            }
    }
    __syncthreads();
    if (tid < 128) {
        float m = fmaxf(redmax[0][tid], redmax[1][tid]);
        float s = redsum[0][tid] + redsum[1][tid];
        g_M[(size_t)bh_*L_ + q0 + tid] = m - s * (1.0f/L_);
    }
}

// ============================================================
__global__ __launch_bounds__(256)
void topk_warp_kernel()
{
    const int warp = threadIdx.x >> 5, lane = threadIdx.x & 31;
    const int bh = blockIdx.x * 8 + warp;
    const float* Mp = g_M + (size_t)bh*L_;
    float v[32];
#pragma unroll
    for (int j = 0; j < 32; j++) v[j] = Mp[j*32 + lane];

    for (int it = 0; it < U_; it++) {
        float bv = v[0]; int bj = 0;
#pragma unroll
        for (int j = 1; j < 32; j++)
            if (v[j] > bv) { bv = v[j]; bj = j; }
        int bk = bj*32 + lane;
#pragma unroll
        for (int off = 16; off; off >>= 1) {
            float ov = __shfl_xor_sync(0xffffffffu, bv, off);
            int   ok = __shfl_xor_sync(0xffffffffu, bk, off);
            if (ov > bv || (ov == bv && ok < bk)) { bv = ov; bk = ok; }
        }
        if (lane == 0) g_idx[bh*U_ + it] = bk;
        int cj = bk >> 5;
        bool mine = ((bk & 31) == lane);
#pragma unroll
        for (int j = 0; j < 32; j++)
            if (mine && j == cj) v[j] = -INF_F;
    }
}

// ============================================================
__global__ __launch_bounds__(256)
void vmean_kernel()
{
    const int bh = blockIdx.x, tid = threadIdx.x;
    const int d = tid & 63, part = tid >> 6;
    const float* vp = g_v + (size_t)bh*L_*D_;
    float acc = 0.f;
    for (int l = part*256; l < part*256 + 256; l++)
        acc += vp[(size_t)l*D_ + d];
    __shared__ float red[4][64];
    red[part][d] = acc;
    __syncthreads();
    if (tid < 64)
        g_vm[bh*64 + tid] =
            (red[0][tid] + red[1][tid] + red[2][tid] + red[3][tid]) * (1.0f/L_);
}

__global__ void zero_kernel()
{
    int t = blockIdx.x*256 + threadIdx.x;
    if (t < B_*L_) g_flag[t] = 0;
    if (t < B_)    g_cnt[t]  = 0;
}

__global__ void compact_kernel()
{
    int t = blockIdx.x*256 + threadIdx.x;
    if (t >= BH_*U_) return;
    int bh = t / U_;
    int b  = bh >> 3;
    int row = g_idx[t];
    if (atomicExch(&g_flag[b*L_ + row], 1) == 0) {
        int p = atomicAdd(&g_cnt[b], 1);
        g_rows[b*L_ + p] = row;
    }
}

__global__ __launch_bounds__(256)
void x2init_kernel()
{
    const int b = blockIdx.x, t = blockIdx.y, tid = threadIdx.x;
    __shared__ float vms[F_];
    for (int f = tid; f < F_; f += 256)
        vms[f] = g_vm[(b*H_ + (f >> 6))*64 + (f & 63)];
    __syncthreads();
    const int cnt = g_cnt[b];
    int hiR = t*128 + 128; if (hiR > cnt) hiR = cnt;
    for (int ri = t*128; ri < hiR; ri++) {
        int l = g_rows[b*L_ + ri];
        float* p = g_x2 + ((size_t)b*L_ + l)*F_;
        p[tid]       = vms[tid];
        p[tid + 256] = vms[tid + 256];
    }
}

// ============================================================
__global__ __launch_bounds__(256)
void sp_scores_kernel(const int* __restrict__ mask)
{
    __shared__ float qs[U_][64];
    __shared__ float Ks[128][68];
    __shared__ int   sidx[U_];
    const int bh = blockIdx.x, tid = threadIdx.x;
    const int b = bh >> 3;
    const int kt0 = blockIdx.y << 7;
    const float* qp = g_q + (size_t)bh*L_*D_;
    const float* kp = g_k + (size_t)bh*L_*D_;
    float* scp = g_sc + (size_t)bh*U_*L_;
    const int* mrow = mask + b*L_;

    if (tid < U_) sidx[tid] = g_idx[bh*U_ + tid];
    __syncthreads();
    for (int i = tid; i < U_*16; i += 256) {
        int u = i >> 4, dc = (i & 15) << 2;
        *(float4*)&qs[u][dc] = *(const float4*)(qp + (size_t)sidx[u]*D_ + dc);
    }
    for (int i = tid; i < 128*16; i += 256) {
        int k = i >> 4, dc = (i & 15) << 2;
        *(float4*)&Ks[k][dc] = *(const float4*)(kp + (size_t)(kt0 + k)*D_ + dc);
    }
    __syncthreads();

    for (int p = tid; p < U_*128; p += 256) {
        int u = p >> 7, kk = p & 127;
        float s = 0.f;
#pragma unroll
        for (int dc = 0; dc < 64; dc += 4) {
            float4 a = *(const float4*)&qs[u][dc];
            float4 c = *(const float4*)&Ks[kk][dc];
            s += a.x*c.x + a.y*c.y + a.z*c.z + a.w*c.w;
        }
        int k = kt0 + kk;
        s *= 0.125f;
        if (mrow[k] == 0) s = -INF_F;
        scp[(size_t)u*L_ + k] = s;
    }
}

__global__ __launch_bounds__(256)
void sp_softmax_kernel()
{
    const int bh = blockIdx.x, tid = threadIdx.x;
    float* scp = g_sc + (size_t)bh*U_*L_;
    const int wid = tid >> 5, lane = tid & 31;
    for (int u = wid; u < U_; u += 8) {
        float mx = -INF_F;
        for (int k = lane; k < L_; k += 32)
            mx = fmaxf(mx, scp[(size_t)u*L_ + k]);
#pragma unroll
        for (int off = 16; off; off >>= 1)
            mx = fmaxf(mx, __shfl_xor_sync(0xffffffffu, mx, off));
        float sm = 0.f;
        for (int k = lane; k < L_; k += 32) {
            float s = scp[(size_t)u*L_ + k];
            sm += (s == -INF_F) ? 0.f : expf(s - mx);
        }
#pragma unroll
        for (int off = 16; off; off >>= 1)
            sm += __shfl_xor_sync(0xffffffffu, sm, off);
        float inv = (sm > 0.f) ? 1.0f / sm : 0.f;
        for (int k = lane; k < L_; k += 32) {
            float s = scp[(size_t)u*L_ + k];
            float pv = (s == -INF_F || mx == -INF_F) ? 0.f : expf(s - mx) * inv;
            scp[(size_t)u*L_ + k] = pv;
        }
    }
}

__global__ __launch_bounds__(256)
void sp_ctx_kernel()
{
    __shared__ float ps[U_][64];
    __shared__ float cb[U_][64];
    __shared__ int   sidx[U_];
    const int bh = blockIdx.x, tid = threadIdx.x;
    const int b = bh >> 3, h = bh & 7;
    const float* vp = g_v + (size_t)bh*L_*D_;
    const float* scp = g_sc + (size_t)bh*U_*L_;
    if (tid < U_) sidx[tid] = g_idx[bh*U_ + tid];

    const int d = tid & 63, part = tid >> 6;
    float acc[U_];
#pragma unroll
    for (int u = 0; u < U_; u++) acc[u] = 0.f;

    for (int kt = 0; kt < L_; kt += 64) {
        __syncthreads();
        for (int i = tid; i < U_*64; i += 256) {
            int u = i >> 6, kk = i & 63;
            ps[u][kk] = scp[(size_t)u*L_ + kt + kk];
        }
        __syncthreads();
        for (int kk = part*16; kk < part*16 + 16; kk++) {
            float v = vp[(size_t)(kt + kk)*D_ + d];
#pragma unroll
            for (int u = 0; u < U_; u++)
                acc[u] += ps[u][kk] * v;
        }
    }
    __syncthreads();
    for (int p2 = 0; p2 < 4; p2++) {
        if (part == p2) {
#pragma unroll
            for (int u = 0; u < U_; u++) {
                if (p2 == 0) cb[u][d] = acc[u];
                else         cb[u][d] += acc[u];
            }
        }
        __syncthreads();
    }
    float* x2 = g_x2 + (size_t)b*L_*F_ + h*D_;
    for (int i = tid; i < U_*64; i += 256) {
        int u = i >> 6, dd = i & 63;
        x2[(size_t)sidx[u]*F_ + dd] = cb[u][dd];
    }
}

// ============================================================
// split compacted x2 rows into dense bf16 buffer g_x2s
// grid (B_, 3), 256 thr; each thread covers 2 cols per row
// ============================================================
__global__ __launch_bounds__(256)
void x2conv_kernel()
{
    const int b = blockIdx.x, t = blockIdx.y, tid = threadIdx.x;
    const int cnt = g_cnt[b];
    const int base = t*128;
    for (int ri = base; ri < base + 128; ri++) {
        __nv_bfloat16* dr = g_x2s + ((size_t)b*RMAX_ + ri)*1024;
        if (ri < cnt) {
            int l = g_rows[b*L_ + ri];
            const float* src = g_x2 + ((size_t)b*L_ + l)*F_;
            float2 v = *(const float2*)(src + tid*2);
            __nv_bfloat16 h0 = __float2bfloat16(v.x);
            __nv_bfloat16 h1 = __float2bfloat16(v.y);
            *(uint32_t*)(dr + tid*2) = pack_bf2(v.x, v.y);
            *(uint32_t*)(dr + 512 + tid*2) =
                pack_bf2(v.x - __bfloat162float(h0), v.y - __bfloat162float(h1));
        } else {
            *(uint32_t*)(dr + tid*2) = 0u;
            *(uint32_t*)(dr + 512 + tid*2) = 0u;
        }
    }
}

// ============================================================
// output GEMM over compacted rows via HMMA split-bf16
// grid (4, B_*3), 8 warps (4m x 2n), scatter epilogue
// ============================================================
__global__ __launch_bounds__(256, 2)
void hmma_rows_kernel(const float* __restrict__ bo, float* __restrict__ out)
{
    __shared__ __align__(16) __nv_bfloat16 Ah[TILE_E];
    __shared__ __align__(16) __nv_bfloat16 Al[TILE_E];
    __shared__ __align__(16) __nv_bfloat16 Bh[TILE_E];
    __shared__ __align__(16) __nv_bfloat16 Bl[TILE_E];
    __shared__ int rows_s[128];

    const int tid = threadIdx.x;
    const int lane = tid & 31, wid = tid >> 5;
    const int b = blockIdx.y / 3, t = blockIdx.y % 3;
    const int cnt = g_cnt[b];
    if (t*128 >= cnt) return;
    const int n0 = blockIdx.x * 128;
    const int wm = (wid >> 1) * 32;
    const int wn = (wid & 1) * 64;

    if (tid < 128) {
        int gi = t*128 + tid;
        rows_s[tid] = (gi < cnt) ? g_rows[b*L_ + gi] : -1;
    }

    const __nv_bfloat16* xc = g_x2s + ((size_t)b*RMAX_ + t*128)*1024;
    const __nv_bfloat16* wc = g_wo;

    float acc[2][8][4];
#pragma unroll
    for (int i = 0; i < 2; i++)
#pragma unroll
        for (int j = 0; j < 8; j++)
#pragma unroll
            for (int c = 0; c < 4; c++) acc[i][j][c] = 0.f;

    const int lrow = lane & 15, lhalf = lane >> 4;
    const uint32_t sAh = smem_u32(Ah), sAl = smem_u32(Al);
    const uint32_t sBh = smem_u32(Bh), sBl = smem_u32(Bl);
    uint32_t aoffH = sAh + (uint32_t)(((wm + lrow)*TS + lhalf*8) * 2);
    uint32_t aoffL = sAl + (uint32_t)(((wm + lrow)*TS + lhalf*8) * 2);
    uint32_t boffH[4], boffL[4];
#pragma unroll
    for (int nq = 0; nq < 4; nq++) {
        boffH[nq] = sBh + (uint32_t)(((wn + nq*16 + lrow)*TS + lhalf*8) * 2);
        boffL[nq] = sBl + (uint32_t)(((wn + nq*16 + lrow)*TS + lhalf*8) * 2);
    }

    for (int kc = 0; kc < 8; kc++) {
        __syncthreads();
#pragma unroll
        for (int it = 0; it < 4; it++) {
            int idx = tid + it*256;
            int row = idx >> 3, c8 = (idx & 7) << 3;
            const __nv_bfloat16* xr = xc + (size_t)row*1024 + kc*64 + c8;
            const __nv_bfloat16* wr = wc + (size_t)(n0 + row)*1024 + kc*64 + c8;
            *(uint4*)(Ah + row*TS + c8) = *(const uint4*)(xr);
            *(uint4*)(Al + row*TS + c8) = *(const uint4*)(xr + 512);
            *(uint4*)(Bh + row*TS + c8) = *(const uint4*)(wr);
            *(uint4*)(Bl + row*TS + c8) = *(const uint4*)(wr + 512);
        }
        __syncthreads();

#pragma unroll
        for (int kt = 0; kt < 4; kt++) {
            const uint32_t kb = kt * 32;
            uint32_t ah[2][4], al[2][4];
            LDSM4(ah[0], aoffH + kb);
            LDSM4(ah[1], aoffH + kb + 16*TS*2);
            LDSM4(al[0], aoffL + kb);
            LDSM4(al[1], aoffL + kb + 16*TS*2);
#pragma unroll
            for (int nq = 0; nq < 4; nq++) {
                uint32_t bh[4], bl[4];
                LDSM4(bh, boffH[nq] + kb);
                LDSM4(bl, boffL[nq] + kb);
                MMA_GROUP(acc[0][nq*2], acc[0][nq*2+1],
                          acc[1][nq*2], acc[1][nq*2+1],
                          ah, al, bh, bl);
            }
        }
    }

    const int r0 = lane >> 2, c0 = (lane & 3) << 1;
#pragma unroll
    for (int mi = 0; mi < 2; mi++) {
        int lA = rows_s[wm + mi*16 + r0];
        int lB = rows_s[wm + mi*16 + r0 + 8];
#pragma unroll
        for (int ni = 0; ni < 8; ni++) {
            int n = n0 + wn + ni*8 + c0;
            float b0v = bo[n], b1v = bo[n+1];
            if (lA >= 0)
                *(float2*)(out + ((size_t)b*L_ + lA)*F_ + n) =
                    make_float2(acc[mi][ni][0] + b0v, acc[mi][ni][1] + b1v);
            if (lB >= 0)
                *(float2*)(out + ((size_t)b*L_ + lB)*F_ + n) =
                    make_float2(acc[mi][ni][2] + b0v, acc[mi][ni][3] + b1v);
        }
    }
}

// ============================================================
__global__ __launch_bounds__(256)
void mean_out_kernel(const float* __restrict__ Wo, const float* __restrict__ bo)
{
    const int b = blockIdx.x, tid = threadIdx.x;
    __shared__ float vms[F_];
    for (int f = tid; f < F_; f += 256)
        vms[f] = g_vm[(b*H_ + (f >> 6))*64 + (f & 63)];
    __syncthreads();
    for (int n = tid; n < F_; n += 256) {
        float s = bo[n];
        const float* w = Wo + (size_t)n*F_;
        for (int f = 0; f < F_; f += 4) {
            float4 wv = *(const float4*)(w + f);
            s += vms[f]*wv.x + vms[f+1]*wv.y + vms[f+2]*wv.z + vms[f+3]*wv.w;
        }
        g_om[b*F_ + n] = s;
    }
}

__global__ __launch_bounds__(256)
void bcast_kernel(float* __restrict__ out)
{
    const int b = blockIdx.x, l0 = blockIdx.y << 3, tid = threadIdx.x;
    __shared__ float om[F_];
    for (int f = tid; f < F_; f += 256) om[f] = g_om[b*F_ + f];
    __syncthreads();
    float2 v = *(const float2*)&om[tid*2];
    float* base = out + ((size_t)b*L_ + l0)*F_;
#pragma unroll
    for (int rr = 0; rr < 8; rr++)
        *(float2*)(base + (size_t)rr*F_ + tid*2) = v;
}

// ============================================================
extern "C" void kernel_launch(void* const* d_in, const int* in_sizes, int n_in,
                              void* d_out, int out_size)
{
    const float* query = (const float*)d_in[0];
    const float* key   = (const float*)d_in[1];
    const float* value = (const float*)d_in[2];
    const int*   mask  = (const int*)  d_in[3];
    const float* Wq = (const float*)d_in[4];
    const float* bq = (const float*)d_in[5];
    const float* Wk = (const float*)d_in[6];
    const float* bk = (const float*)d_in[7];
    const float* Wv = (const float*)d_in[8];
    const float* bv = (const float*)d_in[9];
    const float* Wo = (const float*)d_in[10];
    const float* bo = (const float*)d_in[11];
    float* out = (float*)d_out;

    float *qd, *kd, *vd;
    cudaGetSymbolAddress((void**)&qd, g_q);
    cudaGetSymbolAddress((void**)&kd, g_k);
    cudaGetSymbolAddress((void**)&vd, g_v);

    zero_kernel<<<64, 256>>>();
    convx_kernel<<<dim3((ML_*F_/4)/256, 3), 256>>>(query, key, value);
    convw_kernel<<<dim3((F_*F_/4)/256, 4), 256>>>(Wq, Wk, Wv, Wo);

    hmma_proj_kernel<<<dim3(F_/128, ML_/128, 3), 256>>>(qd, kd, vd, bq, bk, bv);

    qk_hmma_kernel<<<dim3(L_/128, BH_), 256>>>();

    topk_warp_kernel<<<BH_/8, 256>>>();
    vmean_kernel<<<BH_, 256>>>();
    compact_kernel<<<(BH_*U_ + 255)/256, 256>>>();
    x2init_kernel<<<dim3(B_, 3), 256>>>();

    sp_scores_kernel<<<dim3(BH_, 8), 256>>>(mask);
    sp_softmax_kernel<<<BH_, 256>>>();
    sp_ctx_kernel<<<BH_, 256>>>();

    mean_out_kernel<<<B_, 256>>>(Wo, bo);
    bcast_kernel<<<dim3(B_, L_/8), 256>>>(out);

    x2conv_kernel<<<dim3(B_, 3), 256>>>();
    hmma_rows_kernel<<<dim3(F_/128, B_*3), 256>>>(bo, out);
}

// round 13
// speedup vs baseline: 1.0541x; 1.0541x over previous
#include <cuda_runtime.h>
#include <cuda_bf16.h>
#include <cstdint>

typedef unsigned long long u64;

#define B_  16
#define L_  1024
#define F_  512
#define H_  8
#define D_  64
#define U_  35
#define BH_ (B_*H_)
#define ML_ (B_*L_)

#define INF_F __int_as_float(0x7f800000)

// -------- device scratch --------
__device__ float g_q[(size_t)BH_*L_*D_];
__device__ float g_k[(size_t)BH_*L_*D_];
__device__ float g_v[(size_t)BH_*L_*D_];
__device__ float g_M[(size_t)BH_*L_];
__device__ int   g_idx[BH_*U_];
__device__ float g_x2[(size_t)ML_*F_];
__device__ float g_sc[(size_t)BH_*U_*L_];
__device__ float g_vm[BH_*D_];
__device__ float g_om[B_*F_];
__device__ int   g_flag[B_*L_];
__device__ int   g_cnt[B_];
__device__ int   g_rows[B_*L_];
__device__ __nv_bfloat16 g_qs[(size_t)BH_*L_*128];  // q split [hi(64)|lo(64)]
__device__ __nv_bfloat16 g_ks[(size_t)BH_*L_*128];  // k split

// -------- f32x2 helpers --------
__device__ __forceinline__ void fma2(u64 &acc, u64 a, u64 b) {
    asm("fma.rn.f32x2 %0, %1, %2, %0;" : "+l"(acc) : "l"(a), "l"(b));
}
__device__ __forceinline__ u64 dup2(float v) {
    u64 r; asm("mov.b64 %0, {%1, %1};" : "=l"(r) : "f"(v)); return r;
}
__device__ __forceinline__ float2 unpk(u64 v) {
    float2 r; asm("mov.b64 {%0, %1}, %2;" : "=f"(r.x), "=f"(r.y) : "l"(v)); return r;
}

// -------- mma.sync helpers (baseline PTX, sm_80+) --------
__device__ __forceinline__ uint32_t smem_u32(const void* p) {
    uint32_t a;
    asm("{ .reg .u64 t; cvta.to.shared.u64 t, %1; cvt.u32.u64 %0, t; }" : "=r"(a) : "l"(p));
    return a;
}
#define LDSM4(r, addr) \
    asm volatile("ldmatrix.sync.aligned.m8n8.x4.shared.b16 {%0,%1,%2,%3}, [%4];" \
        : "=r"((r)[0]), "=r"((r)[1]), "=r"((r)[2]), "=r"((r)[3]) : "r"(addr))
#define MMA16816(c, a, b0v, b1v) \
    asm("mma.sync.aligned.m16n8k16.row.col.f32.bf16.bf16.f32 " \
        "{%0,%1,%2,%3}, {%4,%5,%6,%7}, {%8,%9}, {%0,%1,%2,%3};" \
        : "+f"((c)[0]), "+f"((c)[1]), "+f"((c)[2]), "+f"((c)[3]) \
        : "r"((a)[0]), "r"((a)[1]), "r"((a)[2]), "r"((a)[3]), "r"(b0v), "r"(b1v))

__device__ __forceinline__ uint32_t pack_bf2(float x, float y) {
    __nv_bfloat162 t;
    t.x = __float2bfloat16(x);
    t.y = __float2bfloat16(y);
    return *(uint32_t*)&t;
}

// split 8 consecutive fp32 into uint4 of bf16-hi and uint4 of bf16-lo
__device__ __forceinline__ void split8(const float* __restrict__ p,
                                       uint4 &hi, uint4 &lo) {
    float4 a = *(const float4*)p;
    float4 b = *(const float4*)(p + 4);
    float v[8] = {a.x, a.y, a.z, a.w, b.x, b.y, b.z, b.w};
    uint32_t hw[4], lw[4];
#pragma unroll
    for (int i = 0; i < 4; i++) {
        float e0 = v[2*i], e1 = v[2*i+1];
        __nv_bfloat16 h0 = __float2bfloat16(e0);
        __nv_bfloat16 h1 = __float2bfloat16(e1);
        __nv_bfloat162 hp; hp.x = h0; hp.y = h1;
        hw[i] = *(uint32_t*)&hp;
        lw[i] = pack_bf2(e0 - __bfloat162float(h0), e1 - __bfloat162float(h1));
    }
    hi = make_uint4(hw[0], hw[1], hw[2], hw[3]);
    lo = make_uint4(lw[0], lw[1], lw[2], lw[3]);
}

// term-major split MMA block (gap-4 chains)
#define MMA_GROUP(accA0, accA1, accB0, accB1, ah, al, bh, bl) do { \
    MMA16816(accA0, (ah)[0], (bh)[0], (bh)[2]); \
    MMA16816(accA1, (ah)[0], (bh)[1], (bh)[3]); \
    MMA16816(accB0, (ah)[1], (bh)[0], (bh)[2]); \
    MMA16816(accB1, (ah)[1], (bh)[1], (bh)[3]); \
    MMA16816(accA0, (ah)[0], (bl)[0], (bl)[2]); \
    MMA16816(accA1, (ah)[0], (bl)[1], (bl)[3]); \
    MMA16816(accB0, (ah)[1], (bl)[0], (bl)[2]); \
    MMA16816(accB1, (ah)[1], (bl)[1], (bl)[3]); \
    MMA16816(accA0, (al)[0], (bh)[0], (bh)[2]); \
    MMA16816(accA1, (al)[0], (bh)[1], (bh)[3]); \
    MMA16816(accB0, (al)[1], (bh)[0], (bh)[2]); \
    MMA16816(accB1, (al)[1], (bh)[1], (bh)[3]); \
} while (0)

// ============================================================
// HMMA projection GEMM with fused fp32->bf16 split loads.
// CTA 128x128, 8 warps (4m x 2n), warp tile 32x64, k-chunk 64.
// z<2 epilogue also emits bf16 hi/lo split rows (g_qs/g_ks).
// ============================================================
#define TS 72
#define TILE_E (128*TS)

__global__ __launch_bounds__(256, 2)
void hmma_proj_kernel(const float* __restrict__ xq, const float* __restrict__ xk,
                      const float* __restrict__ xv,
                      const float* __restrict__ wq, const float* __restrict__ wk,
                      const float* __restrict__ wv,
                      float* qd, float* kd, float* vd,
                      const float* __restrict__ bq,
                      const float* __restrict__ bk,
                      const float* __restrict__ bv)
{
    __shared__ __align__(16) __nv_bfloat16 Ah[TILE_E];
    __shared__ __align__(16) __nv_bfloat16 Al[TILE_E];
    __shared__ __align__(16) __nv_bfloat16 Bh[TILE_E];
    __shared__ __align__(16) __nv_bfloat16 Bl[TILE_E];

    const int tid = threadIdx.x;
    const int lane = tid & 31, wid = tid >> 5;
    const int z = blockIdx.z;
    const int m0 = blockIdx.y * 128, n0 = blockIdx.x * 128;
    const int wm = (wid >> 1) * 32;
    const int wn = (wid & 1) * 64;

    const float* X = (z == 0) ? xq : (z == 1) ? xk : xv;
    const float* W = (z == 0) ? wq : (z == 1) ? wk : wv;
    float* dst = (z == 0) ? qd : (z == 1) ? kd : vd;
    const float* bias = (z == 0) ? bq : (z == 1) ? bk : bv;

    float acc[2][8][4];
#pragma unroll
    for (int i = 0; i < 2; i++)
#pragma unroll
        for (int j = 0; j < 8; j++)
#pragma unroll
            for (int c = 0; c < 4; c++) acc[i][j][c] = 0.f;

    const int lrow = lane & 15, lhalf = lane >> 4;
    const uint32_t sAh = smem_u32(Ah), sAl = smem_u32(Al);
    const uint32_t sBh = smem_u32(Bh), sBl = smem_u32(Bl);
    uint32_t aoffH = sAh + (uint32_t)(((wm + lrow)*TS + lhalf*8) * 2);
    uint32_t aoffL = sAl + (uint32_t)(((wm + lrow)*TS + lhalf*8) * 2);
    uint32_t boffH[4], boffL[4];
#pragma unroll
    for (int nq = 0; nq < 4; nq++) {
        boffH[nq] = sBh + (uint32_t)(((wn + nq*16 + lrow)*TS + lhalf*8) * 2);
        boffL[nq] = sBl + (uint32_t)(((wn + nq*16 + lrow)*TS + lhalf*8) * 2);
    }

    const int ldrow = tid >> 3, ldc8 = (tid & 7) << 3;

    for (int kc = 0; kc < 8; kc++) {
        __syncthreads();
#pragma unroll
        for (int it = 0; it < 4; it++) {
            int row = ldrow + it*32;
            const float* xr = X + (size_t)(m0 + row)*F_ + kc*64 + ldc8;
            const float* wr = W + (size_t)(n0 + row)*F_ + kc*64 + ldc8;
            uint4 hi, lo;
            split8(xr, hi, lo);
            *(uint4*)(Ah + row*TS + ldc8) = hi;
            *(uint4*)(Al + row*TS + ldc8) = lo;
            split8(wr, hi, lo);
            *(uint4*)(Bh + row*TS + ldc8) = hi;
            *(uint4*)(Bl + row*TS + ldc8) = lo;
        }
        __syncthreads();

#pragma unroll
        for (int kt = 0; kt < 4; kt++) {
            const uint32_t kb = kt * 32;
            uint32_t ah[2][4], al[2][4];
            LDSM4(ah[0], aoffH + kb);
            LDSM4(ah[1], aoffH + kb + 16*TS*2);
            LDSM4(al[0], aoffL + kb);
            LDSM4(al[1], aoffL + kb + 16*TS*2);
#pragma unroll
            for (int nq = 0; nq < 4; nq++) {
                uint32_t bh[4], bl[4];
                LDSM4(bh, boffH[nq] + kb);
                LDSM4(bl, boffL[nq] + kb);
                MMA_GROUP(acc[0][nq*2], acc[0][nq*2+1],
                          acc[1][nq*2], acc[1][nq*2+1],
                          ah, al, bh, bl);
            }
        }
    }

    // ---- epilogue: fp32 out + (z<2) bf16 hi/lo split out ----
    __nv_bfloat16* sp = (z == 0) ? g_qs : g_ks;
    const int r0 = lane >> 2, c0 = (lane & 3) << 1;
#pragma unroll
    for (int mi = 0; mi < 2; mi++) {
        int mA = m0 + wm + mi*16 + r0;
        int mB = mA + 8;
        int bA = mA >> 10, lA = mA & (L_-1);
        int bB = mB >> 10, lB = mB & (L_-1);
#pragma unroll
        for (int ni = 0; ni < 8; ni++) {
            int n = n0 + wn + ni*8 + c0;
            int h = n >> 6, d = n & 63;
            float b0v = bias[n], b1v = bias[n+1];
            float vA0 = acc[mi][ni][0] + b0v, vA1 = acc[mi][ni][1] + b1v;
            float vB0 = acc[mi][ni][2] + b0v, vB1 = acc[mi][ni][3] + b1v;
            size_t rowA = (size_t)(bA*H_ + h)*L_ + lA;
            size_t rowB = (size_t)(bB*H_ + h)*L_ + lB;
            *(float2*)(dst + rowA*D_ + d) = make_float2(vA0, vA1);
            *(float2*)(dst + rowB*D_ + d) = make_float2(vB0, vB1);
            if (z < 2) {
                float hA0 = __bfloat162float(__float2bfloat16(vA0));
                float hA1 = __bfloat162float(__float2bfloat16(vA1));
                float hB0 = __bfloat162float(__float2bfloat16(vB0));
                float hB1 = __bfloat162float(__float2bfloat16(vB1));
                __nv_bfloat16* pA = sp + rowA*128 + d;
                __nv_bfloat16* pB = sp + rowB*128 + d;
                *(uint32_t*)pA        = pack_bf2(vA0, vA1);
                *(uint32_t*)(pA + 64) = pack_bf2(vA0 - hA0, vA1 - hA1);
                *(uint32_t*)pB        = pack_bf2(vB0, vB1);
                *(uint32_t*)(pB + 64) = pack_bf2(vB0 - hB0, vB1 - hB1);
            }
        }
    }
}

// ============================================================
// qk M kernel via HMMA split-bf16 (static smem, 2 CTAs/SM)
// ============================================================
__global__ __launch_bounds__(256, 2)
void qk_hmma_kernel()
{
    __shared__ __align__(16) __nv_bfloat16 Qh[TILE_E];
    __shared__ __align__(16) __nv_bfloat16 Ql[TILE_E];
    __shared__ __align__(16) __nv_bfloat16 Kh[TILE_E];
    __shared__ __align__(16) __nv_bfloat16 Kl[TILE_E];
    __shared__ float redmax[2][128];
    __shared__ float redsum[2][128];

    const int tid = threadIdx.x;
    const int lane = tid & 31, wid = tid >> 5;
    const int bh_ = blockIdx.y, q0 = blockIdx.x * 128;
    const int wm = (wid >> 1) * 32, wn = (wid & 1) * 64;

    const __nv_bfloat16* qs = g_qs + (size_t)bh_*L_*128;
    const __nv_bfloat16* ks = g_ks + (size_t)bh_*L_*128;

#pragma unroll
    for (int it = 0; it < 4; it++) {
        int idx = tid + it*256;
        int row = idx >> 3, c8 = (idx & 7) << 3;
        const __nv_bfloat16* src = qs + (size_t)(q0 + row)*128 + c8;
        *(uint4*)(Qh + row*TS + c8) = *(const uint4*)(src);
        *(uint4*)(Ql + row*TS + c8) = *(const uint4*)(src + 64);
    }

    const int lrow = lane & 15, lhalf = lane >> 4;
    const uint32_t sQh = smem_u32(Qh), sQl = smem_u32(Ql);
    const uint32_t sKh = smem_u32(Kh), sKl = smem_u32(Kl);
    uint32_t aoffH = sQh + (uint32_t)(((wm + lrow)*TS + lhalf*8) * 2);
    uint32_t aoffL = sQl + (uint32_t)(((wm + lrow)*TS + lhalf*8) * 2);
    uint32_t boffH[4], boffL[4];
#pragma unroll
    for (int nq = 0; nq < 4; nq++) {
        boffH[nq] = sKh + (uint32_t)(((wn + nq*16 + lrow)*TS + lhalf*8) * 2);
        boffL[nq] = sKl + (uint32_t)(((wn + nq*16 + lrow)*TS + lhalf*8) * 2);
    }

    float rmax_[2][2], rsum_[2][2];
#pragma unroll
    for (int i = 0; i < 2; i++)
#pragma unroll
        for (int j = 0; j < 2; j++) { rmax_[i][j] = -INF_F; rsum_[i][j] = 0.f; }

    for (int kt = 0; kt < 8; kt++) {
        __syncthreads();
#pragma unroll
        for (int it = 0; it < 4; it++) {
            int idx = tid + it*256;
            int row = idx >> 3, c8 = (idx & 7) << 3;
            const __nv_bfloat16* src = ks + (size_t)(kt*128 + row)*128 + c8;
            *(uint4*)(Kh + row*TS + c8) = *(const uint4*)(src);
            *(uint4*)(Kl + row*TS + c8) = *(const uint4*)(src + 64);
        }
        __syncthreads();

        float acc[2][8][4];
#pragma unroll
        for (int i = 0; i < 2; i++)
#pragma unroll
            for (int j = 0; j < 8; j++)
#pragma unroll
                for (int c = 0; c < 4; c++) acc[i][j][c] = 0.f;

#pragma unroll
        for (int k16 = 0; k16 < 4; k16++) {
            const uint32_t kb = k16 * 32;
            uint32_t ah[2][4], al[2][4];
            LDSM4(ah[0], aoffH + kb);
            LDSM4(ah[1], aoffH + kb + 16*TS*2);
            LDSM4(al[0], aoffL + kb);
            LDSM4(al[1], aoffL + kb + 16*TS*2);
#pragma unroll
            for (int nq = 0; nq < 4; nq++) {
                uint32_t bhf[4], blf[4];
                LDSM4(bhf, boffH[nq] + kb);
                LDSM4(blf, boffL[nq] + kb);
                MMA_GROUP(acc[0][nq*2], acc[0][nq*2+1],
                          acc[1][nq*2], acc[1][nq*2+1],
                          ah, al, bhf, blf);
            }
        }

#pragma unroll
        for (int mi = 0; mi < 2; mi++) {
            float m0 = -INF_F, m1 = -INF_F, s0 = 0.f, s1 = 0.f;
#pragma unroll
            for (int ni = 0; ni < 8; ni++) {
                m0 = fmaxf(m0, fmaxf(acc[mi][ni][0], acc[mi][ni][1]));
                s0 += acc[mi][ni][0] + acc[mi][ni][1];
                m1 = fmaxf(m1, fmaxf(acc[mi][ni][2], acc[mi][ni][3]));
                s1 += acc[mi][ni][2] + acc[mi][ni][3];
            }
            rmax_[mi][0] = fmaxf(rmax_[mi][0], m0); rsum_[mi][0] += s0;
            rmax_[mi][1] = fmaxf(rmax_[mi][1], m1); rsum_[mi][1] += s1;
        }
    }

#pragma unroll
    for (int mi = 0; mi < 2; mi++)
#pragma unroll
        for (int hf = 0; hf < 2; hf++) {
            float m = rmax_[mi][hf], s = rsum_[mi][hf];
#pragma unroll
            for (int off = 1; off <= 2; off <<= 1) {
                m = fmaxf(m, __shfl_xor_sync(0xffffffffu, m, off));
                s += __shfl_xor_sync(0xffffffffu, s, off);
            }
            rmax_[mi][hf] = m; rsum_[mi][hf] = s;
        }
    if ((lane & 3) == 0) {
        int r0 = lane >> 2;
#pragma unroll
        for (int mi = 0; mi < 2; mi++)
#pragma unroll
            for (int hf = 0; hf < 2; hf++) {
                int row = wm + mi*16 + hf*8 + r0;
                redmax[wid & 1][row] = rmax_[mi][hf];
                redsum[wid & 1][row] = rsum_[mi][hf];
            }
    }
    __syncthreads();
    if (tid < 128) {
        float m = fmaxf(redmax[0][tid], redmax[1][tid]);
        float s = redsum[0][tid] + redsum[1][tid];
        g_M[(size_t)bh_*L_ + q0 + tid] = m - s * (1.0f/L_);
    }
}

// ============================================================
__global__ __launch_bounds__(256)
void topk_warp_kernel()
{
    const int warp = threadIdx.x >> 5, lane = threadIdx.x & 31;
    const int bh = blockIdx.x * 8 + warp;
    const float* Mp = g_M + (size_t)bh*L_;
    float v[32];
#pragma unroll
    for (int j = 0; j < 32; j++) v[j] = Mp[j*32 + lane];

    for (int it = 0; it < U_; it++) {
        float bv = v[0]; int bj = 0;
#pragma unroll
        for (int j = 1; j < 32; j++)
            if (v[j] > bv) { bv = v[j]; bj = j; }
        int bk = bj*32 + lane;
#pragma unroll
        for (int off = 16; off; off >>= 1) {
            float ov = __shfl_xor_sync(0xffffffffu, bv, off);
            int   ok = __shfl_xor_sync(0xffffffffu, bk, off);
            if (ov > bv || (ov == bv && ok < bk)) { bv = ov; bk = ok; }
        }
        if (lane == 0) g_idx[bh*U_ + it] = bk;
        int cj = bk >> 5;
        bool mine = ((bk & 31) == lane);
#pragma unroll
        for (int j = 0; j < 32; j++)
            if (mine && j == cj) v[j] = -INF_F;
    }
}

// ============================================================
__global__ __launch_bounds__(256)
void vmean_kernel()
{
    const int bh = blockIdx.x, tid = threadIdx.x;
    const int d = tid & 63, part = tid >> 6;
    const float* vp = g_v + (size_t)bh*L_*D_;
    float acc = 0.f;
    for (int l = part*256; l < part*256 + 256; l++)
        acc += vp[(size_t)l*D_ + d];
    __shared__ float red[4][64];
    red[part][d] = acc;
    __syncthreads();
    if (tid < 64)
        g_vm[bh*64 + tid] =
            (red[0][tid] + red[1][tid] + red[2][tid] + red[3][tid]) * (1.0f/L_);
}

__global__ void zero_kernel()
{
    int t = blockIdx.x*256 + threadIdx.x;
    if (t < B_*L_) g_flag[t] = 0;
    if (t < B_)    g_cnt[t]  = 0;
}

__global__ void compact_kernel()
{
    int t = blockIdx.x*256 + threadIdx.x;
    if (t >= BH_*U_) return;
    int bh = t / U_;
    int b  = bh >> 3;
    int row = g_idx[t];
    if (atomicExch(&g_flag[b*L_ + row], 1) == 0) {
        int p = atomicAdd(&g_cnt[b], 1);
        g_rows[b*L_ + p] = row;
    }
}

__global__ __launch_bounds__(256)
void x2init_kernel()
{
    const int b = blockIdx.x, t = blockIdx.y, tid = threadIdx.x;
    __shared__ float vms[F_];
    for (int f = tid; f < F_; f += 256)
        vms[f] = g_vm[(b*H_ + (f >> 6))*64 + (f & 63)];
    __syncthreads();
    const int cnt = g_cnt[b];
    int hiR = t*128 + 128; if (hiR > cnt) hiR = cnt;
    for (int ri = t*128; ri < hiR; ri++) {
        int l = g_rows[b*L_ + ri];
        float* p = g_x2 + ((size_t)b*L_ + l)*F_;
        p[tid]       = vms[tid];
        p[tid + 256] = vms[tid + 256];
    }
}

// ============================================================
__global__ __launch_bounds__(256)
void sp_scores_kernel(const int* __restrict__ mask)
{
    __shared__ float qs[U_][64];
    __shared__ float Ks[128][68];
    __shared__ int   sidx[U_];
    const int bh = blockIdx.x, tid = threadIdx.x;
    const int b = bh >> 3;
    const int kt0 = blockIdx.y << 7;
    const float* qp = g_q + (size_t)bh*L_*D_;
    const float* kp = g_k + (size_t)bh*L_*D_;
    float* scp = g_sc + (size_t)bh*U_*L_;
    const int* mrow = mask + b*L_;

    if (tid < U_) sidx[tid] = g_idx[bh*U_ + tid];
    __syncthreads();
    for (int i = tid; i < U_*16; i += 256) {
        int u = i >> 4, dc = (i & 15) << 2;
        *(float4*)&qs[u][dc] = *(const float4*)(qp + (size_t)sidx[u]*D_ + dc);
    }
    for (int i = tid; i < 128*16; i += 256) {
        int k = i >> 4, dc = (i & 15) << 2;
        *(float4*)&Ks[k][dc] = *(const float4*)(kp + (size_t)(kt0 + k)*D_ + dc);
    }
    __syncthreads();

    for (int p = tid; p < U_*128; p += 256) {
        int u = p >> 7, kk = p & 127;
        float s = 0.f;
#pragma unroll
        for (int dc = 0; dc < 64; dc += 4) {
            float4 a = *(const float4*)&qs[u][dc];
            float4 c = *(const float4*)&Ks[kk][dc];
            s += a.x*c.x + a.y*c.y + a.z*c.z + a.w*c.w;
        }
        int k = kt0 + kk;
        s *= 0.125f;
        if (mrow[k] == 0) s = -INF_F;
        scp[(size_t)u*L_ + k] = s;
    }
}

__global__ __launch_bounds__(256)
void sp_softmax_kernel()
{
    const int bh = blockIdx.x, tid = threadIdx.x;
    float* scp = g_sc + (size_t)bh*U_*L_;
    const int wid = tid >> 5, lane = tid & 31;
    for (int u = wid; u < U_; u += 8) {
        float mx = -INF_F;
        for (int k = lane; k < L_; k += 32)
            mx = fmaxf(mx, scp[(size_t)u*L_ + k]);
#pragma unroll
        for (int off = 16; off; off >>= 1)
            mx = fmaxf(mx, __shfl_xor_sync(0xffffffffu, mx, off));
        float sm = 0.f;
        for (int k = lane; k < L_; k += 32) {
            float s = scp[(size_t)u*L_ + k];
            sm += (s == -INF_F) ? 0.f : expf(s - mx);
        }
#pragma unroll
        for (int off = 16; off; off >>= 1)
            sm += __shfl_xor_sync(0xffffffffu, sm, off);
        float inv = (sm > 0.f) ? 1.0f / sm : 0.f;
        for (int k = lane; k < L_; k += 32) {
            float s = scp[(size_t)u*L_ + k];
            float pv = (s == -INF_F || mx == -INF_F) ? 0.f : expf(s - mx) * inv;
            scp[(size_t)u*L_ + k] = pv;
        }
    }
}

__global__ __launch_bounds__(256)
void sp_ctx_kernel()
{
    __shared__ float ps[U_][64];
    __shared__ float cb[U_][64];
    __shared__ int   sidx[U_];
    const int bh = blockIdx.x, tid = threadIdx.x;
    const int b = bh >> 3, h = bh & 7;
    const float* vp = g_v + (size_t)bh*L_*D_;
    const float* scp = g_sc + (size_t)bh*U_*L_;
    if (tid < U_) sidx[tid] = g_idx[bh*U_ + tid];

    const int d = tid & 63, part = tid >> 6;
    float acc[U_];
#pragma unroll
    for (int u = 0; u < U_; u++) acc[u] = 0.f;

    for (int kt = 0; kt < L_; kt += 64) {
        __syncthreads();
        for (int i = tid; i < U_*64; i += 256) {
            int u = i >> 6, kk = i & 63;
            ps[u][kk] = scp[(size_t)u*L_ + kt + kk];
        }
        __syncthreads();
        for (int kk = part*16; kk < part*16 + 16; kk++) {
            float v = vp[(size_t)(kt + kk)*D_ + d];
#pragma unroll
            for (int u = 0; u < U_; u++)
                acc[u] += ps[u][kk] * v;
        }
    }
    __syncthreads();
    for (int p2 = 0; p2 < 4; p2++) {
        if (part == p2) {
#pragma unroll
            for (int u = 0; u < U_; u++) {
                if (p2 == 0) cb[u][d] = acc[u];
                else         cb[u][d] += acc[u];
            }
        }
        __syncthreads();
    }
    float* x2 = g_x2 + (size_t)b*L_*F_ + h*D_;
    for (int i = tid; i < U_*64; i += 256) {
        int u = i >> 6, dd = i & 63;
        x2[(size_t)sidx[u]*F_ + dd] = cb[u][dd];
    }
}

// ============================================================
// per-batch mean output row; grid (B_, 4), 2 threads per n
// ============================================================
__global__ __launch_bounds__(256)
void mean_out_kernel(const float* __restrict__ Wo, const float* __restrict__ bo)
{
    const int b = blockIdx.x, t = blockIdx.y, tid = threadIdx.x;
    __shared__ float vms[F_];
    __shared__ float red[128];
    for (int f = tid; f < F_; f += 256)
        vms[f] = g_vm[(b*H_ + (f >> 6))*64 + (f & 63)];
    __syncthreads();
    const int half = tid >> 7, nloc = tid & 127;
    const int n = t*128 + nloc;
    const float* w = Wo + (size_t)n*F_ + half*256;
    const float* vv = vms + half*256;
    float s = 0.f;
#pragma unroll 8
    for (int f = 0; f < 256; f += 4) {
        float4 wv = *(const float4*)(w + f);
        s += vv[f]*wv.x + vv[f+1]*wv.y + vv[f+2]*wv.z + vv[f+3]*wv.w;
    }
    if (half) red[nloc] = s;
    __syncthreads();
    if (!half) g_om[b*F_ + n] = s + red[nloc] + bo[n];
}

__global__ __launch_bounds__(256)
void bcast_kernel(float* __restrict__ out)
{
    const int b = blockIdx.x, l0 = blockIdx.y << 3, tid = threadIdx.x;
    __shared__ float om[F_];
    for (int f = tid; f < F_; f += 256) om[f] = g_om[b*F_ + f];
    __syncthreads();
    float2 v = *(const float2*)&om[tid*2];
    float* base = out + ((size_t)b*L_ + l0)*F_;
#pragma unroll
    for (int rr = 0; rr < 8; rr++)
        *(float2*)(base + (size_t)rr*F_ + tid*2) = v;
}

// ============================================================
// output GEMM over selected rows (fp32 f32x2, R11 form)
// ============================================================
__global__ __launch_bounds__(256, 2)
void gemm_rows_kernel(const float* __restrict__ W,
                      const float* __restrict__ bias,
                      float* __restrict__ out)
{
    const int b = blockIdx.y / 3;
    const int t = blockIdx.y % 3;
    const int cnt = g_cnt[b];
    if (t * 128 >= cnt) return;

    __shared__ __align__(16) float As[2][16][132];
    __shared__ __align__(16) float Bs[2][16][132];
    __shared__ int rows_s[128];

    const int tid = threadIdx.x;
    if (tid < 128) {
        int gi = t*128 + tid;
        rows_s[tid] = (gi < cnt) ? g_rows[b*L_ + gi] : g_rows[b*L_];
    }
    __syncthreads();

    const float* X = g_x2 + (size_t)b*L_*F_;
    const int tx = tid & 15, ty = tid >> 4;
    const int n0 = blockIdx.x * 128;
    const int r  = tid >> 2;
    const int kc = (tid & 3) << 2;
    const int mo = r << 1;
    const int l0r = rows_s[r], l1r = rows_s[r + 64];

    u64 acc[4][8];
#pragma unroll
    for (int i = 0; i < 4; i++)
#pragma unroll
        for (int j = 0; j < 8; j++) acc[i][j] = 0ULL;

    float4 ra0, ra1, rb0, rb1;
    ra0 = *(const float4*)(X + (size_t)l0r*F_ + kc);
    ra1 = *(const float4*)(X + (size_t)l1r*F_ + kc);
    rb0 = *(const float4*)(W + (size_t)(n0 + r)*F_ + kc);
    rb1 = *(const float4*)(W + (size_t)(n0 + r + 64)*F_ + kc);

#define GSTORE(bsel) do { \
    As[bsel][kc+0][mo]   = ra0.x; As[bsel][kc+1][mo]   = ra0.y; \
    As[bsel][kc+2][mo]   = ra0.z; As[bsel][kc+3][mo]   = ra0.w; \
    As[bsel][kc+0][mo+1] = ra1.x; As[bsel][kc+1][mo+1] = ra1.y; \
    As[bsel][kc+2][mo+1] = ra1.z; As[bsel][kc+3][mo+1] = ra1.w; \
    Bs[bsel][kc+0][r]    = rb0.x; Bs[bsel][kc+1][r]    = rb0.y; \
    Bs[bsel][kc+2][r]    = rb0.z; Bs[bsel][kc+3][r]    = rb0.w; \
    Bs[bsel][kc+0][r+64] = rb1.x; Bs[bsel][kc+1][r+64] = rb1.y; \
    Bs[bsel][kc+2][r+64] = rb1.z; Bs[bsel][kc+3][r+64] = rb1.w; } while(0)

    GSTORE(0);
    __syncthreads();

    for (int c = 0; c < 32; c++) {
        if (c < 31) {
            int kb = (c + 1) << 4;
            ra0 = *(const float4*)(X + (size_t)l0r*F_ + kb + kc);
            ra1 = *(const float4*)(X + (size_t)l1r*F_ + kb + kc);
            rb0 = *(const float4*)(W + (size_t)(n0 + r)*F_ + kb + kc);
            rb1 = *(const float4*)(W + (size_t)(n0 + r + 64)*F_ + kb + kc);
        }
        const int bsel = c & 1;
#pragma unroll
        for (int kk = 0; kk < 16; kk++) {
            ulonglong2 a01 = *(const ulonglong2*)&As[bsel][kk][ty << 3];
            ulonglong2 a23 = *(const ulonglong2*)&As[bsel][kk][(ty << 3) + 4];
            float4 b0 = *(const float4*)&Bs[bsel][kk][tx << 3];
            float4 b1 = *(const float4*)&Bs[bsel][kk][(tx << 3) + 4];
            u64 av[4] = {a01.x, a01.y, a23.x, a23.y};
            u64 bv[8] = {dup2(b0.x), dup2(b0.y), dup2(b0.z), dup2(b0.w),
                         dup2(b1.x), dup2(b1.y), dup2(b1.z), dup2(b1.w)};
#pragma unroll
            for (int i = 0; i < 4; i++)
#pragma unroll
                for (int j = 0; j < 8; j++)
                    fma2(acc[i][j], av[i], bv[j]);
        }
        if (c < 31) GSTORE((c + 1) & 1);
        __syncthreads();
    }
#undef GSTORE

    const int nb = n0 + (tx << 3);
    float bb[8];
#pragma unroll
    for (int j = 0; j < 8; j++) bb[j] = bias[nb + j];

#pragma unroll
    for (int i = 0; i < 4; i++) {
        float lo[8], hi[8];
#pragma unroll
        for (int j = 0; j < 8; j++) {
            float2 tt = unpk(acc[i][j]);
            lo[j] = tt.x + bb[j];
            hi[j] = tt.y + bb[j];
        }
        {
            int l = rows_s[(ty << 2) + i];
            float* p = out + ((size_t)b*L_ + l)*F_ + nb;
            *(float4*)p     = make_float4(lo[0], lo[1], lo[2], lo[3]);
            *(float4*)(p+4) = make_float4(lo[4], lo[5], lo[6], lo[7]);
        }
        {
            int l = rows_s[(ty << 2) + i + 64];
            float* p = out + ((size_t)b*L_ + l)*F_ + nb;
            *(float4*)p     = make_float4(hi[0], hi[1], hi[2], hi[3]);
            *(float4*)(p+4) = make_float4(hi[4], hi[5], hi[6], hi[7]);
        }
    }
}

// ============================================================
extern "C" void kernel_launch(void* const* d_in, const int* in_sizes, int n_in,
                              void* d_out, int out_size)
{
    const float* query = (const float*)d_in[0];
    const float* key   = (const float*)d_in[1];
    const float* value = (const float*)d_in[2];
    const int*   mask  = (const int*)  d_in[3];
    const float* Wq = (const float*)d_in[4];
    const float* bq = (const float*)d_in[5];
    const float* Wk = (const float*)d_in[6];
    const float* bk = (const float*)d_in[7];
    const float* Wv = (const float*)d_in[8];
    const float* bv = (const float*)d_in[9];
    const float* Wo = (const float*)d_in[10];
    const float* bo = (const float*)d_in[11];
    float* out = (float*)d_out;

    float *qd, *kd, *vd;
    cudaGetSymbolAddress((void**)&qd, g_q);
    cudaGetSymbolAddress((void**)&kd, g_k);
    cudaGetSymbolAddress((void**)&vd, g_v);

    zero_kernel<<<64, 256>>>();

    hmma_proj_kernel<<<dim3(F_/128, ML_/128, 3), 256>>>(
        query, key, value, Wq, Wk, Wv, qd, kd, vd, bq, bk, bv);

    qk_hmma_kernel<<<dim3(L_/128, BH_), 256>>>();

    topk_warp_kernel<<<BH_/8, 256>>>();
    vmean_kernel<<<BH_, 256>>>();
    compact_kernel<<<(BH_*U_ + 255)/256, 256>>>();
    x2init_kernel<<<dim3(B_, 3), 256>>>();

    sp_scores_kernel<<<dim3(BH_, 8), 256>>>(mask);
    sp_softmax_kernel<<<BH_, 256>>>();
    sp_ctx_kernel<<<BH_, 256>>>();

    mean_out_kernel<<<dim3(B_, 4), 256>>>(Wo, bo);
    bcast_kernel<<<dim3(B_, L_/8), 256>>>(out);
    gemm_rows_kernel<<<dim3(F_/128, B_*3), 256>>>(Wo, bo, out);
}

// round 14
// speedup vs baseline: 1.1948x; 1.1335x over previous
#include <cuda_runtime.h>
#include <cuda_bf16.h>
#include <cstdint>

typedef unsigned long long u64;

#define B_  16
#define L_  1024
#define F_  512
#define H_  8
#define D_  64
#define U_  35
#define BH_ (B_*H_)
#define ML_ (B_*L_)

#define INF_F __int_as_float(0x7f800000)

// -------- device scratch --------
__device__ float g_q[(size_t)BH_*L_*D_];
__device__ float g_k[(size_t)BH_*L_*D_];
__device__ float g_v[(size_t)BH_*L_*D_];
__device__ float g_M[(size_t)BH_*L_];
__device__ int   g_idx[BH_*U_];
__device__ float g_x2[(size_t)ML_*F_];
__device__ float g_sc[(size_t)BH_*U_*L_];
__device__ float g_vm[BH_*D_];
__device__ float g_om[B_*F_];
__device__ int   g_flag[B_*L_];
__device__ int   g_cnt[B_];
__device__ int   g_rows[B_*L_];
__device__ __nv_bfloat16 g_qs[(size_t)BH_*L_*128];  // q split [hi(64)|lo(64)]
__device__ __nv_bfloat16 g_ks[(size_t)BH_*L_*128];  // k split
__device__ float g_cval[BH_*2*U_];                   // topk phase-1 candidates
__device__ int   g_cidx[BH_*2*U_];
__device__ float g_ctxp[4ULL*BH_*U_*64];             // sp_ctx partials

// -------- f32x2 helpers --------
__device__ __forceinline__ void fma2(u64 &acc, u64 a, u64 b) {
    asm("fma.rn.f32x2 %0, %1, %2, %0;" : "+l"(acc) : "l"(a), "l"(b));
}
__device__ __forceinline__ u64 dup2(float v) {
    u64 r; asm("mov.b64 %0, {%1, %1};" : "=l"(r) : "f"(v)); return r;
}
__device__ __forceinline__ float2 unpk(u64 v) {
    float2 r; asm("mov.b64 {%0, %1}, %2;" : "=f"(r.x), "=f"(r.y) : "l"(v)); return r;
}

// -------- mma.sync helpers (baseline PTX, sm_80+) --------
__device__ __forceinline__ uint32_t smem_u32(const void* p) {
    uint32_t a;
    asm("{ .reg .u64 t; cvta.to.shared.u64 t, %1; cvt.u32.u64 %0, t; }" : "=r"(a) : "l"(p));
    return a;
}
#define LDSM4(r, addr) \
    asm volatile("ldmatrix.sync.aligned.m8n8.x4.shared.b16 {%0,%1,%2,%3}, [%4];" \
        : "=r"((r)[0]), "=r"((r)[1]), "=r"((r)[2]), "=r"((r)[3]) : "r"(addr))
#define MMA16816(c, a, b0v, b1v) \
    asm("mma.sync.aligned.m16n8k16.row.col.f32.bf16.bf16.f32 " \
        "{%0,%1,%2,%3}, {%4,%5,%6,%7}, {%8,%9}, {%0,%1,%2,%3};" \
        : "+f"((c)[0]), "+f"((c)[1]), "+f"((c)[2]), "+f"((c)[3]) \
        : "r"((a)[0]), "r"((a)[1]), "r"((a)[2]), "r"((a)[3]), "r"(b0v), "r"(b1v))

__device__ __forceinline__ uint32_t pack_bf2(float x, float y) {
    __nv_bfloat162 t;
    t.x = __float2bfloat16(x);
    t.y = __float2bfloat16(y);
    return *(uint32_t*)&t;
}

// split 8 consecutive fp32 into uint4 of bf16-hi and uint4 of bf16-lo
__device__ __forceinline__ void split8(const float* __restrict__ p,
                                       uint4 &hi, uint4 &lo) {
    float4 a = *(const float4*)p;
    float4 b = *(const float4*)(p + 4);
    float v[8] = {a.x, a.y, a.z, a.w, b.x, b.y, b.z, b.w};
    uint32_t hw[4], lw[4];
#pragma unroll
    for (int i = 0; i < 4; i++) {
        float e0 = v[2*i], e1 = v[2*i+1];
        __nv_bfloat16 h0 = __float2bfloat16(e0);
        __nv_bfloat16 h1 = __float2bfloat16(e1);
        __nv_bfloat162 hp; hp.x = h0; hp.y = h1;
        hw[i] = *(uint32_t*)&hp;
        lw[i] = pack_bf2(e0 - __bfloat162float(h0), e1 - __bfloat162float(h1));
    }
    hi = make_uint4(hw[0], hw[1], hw[2], hw[3]);
    lo = make_uint4(lw[0], lw[1], lw[2], lw[3]);
}

// term-major split MMA block (gap-4 chains)
#define MMA_GROUP(accA0, accA1, accB0, accB1, ah, al, bh, bl) do { \
    MMA16816(accA0, (ah)[0], (bh)[0], (bh)[2]); \
    MMA16816(accA1, (ah)[0], (bh)[1], (bh)[3]); \
    MMA16816(accB0, (ah)[1], (bh)[0], (bh)[2]); \
    MMA16816(accB1, (ah)[1], (bh)[1], (bh)[3]); \
    MMA16816(accA0, (ah)[0], (bl)[0], (bl)[2]); \
    MMA16816(accA1, (ah)[0], (bl)[1], (bl)[3]); \
    MMA16816(accB0, (ah)[1], (bl)[0], (bl)[2]); \
    MMA16816(accB1, (ah)[1], (bl)[1], (bl)[3]); \
    MMA16816(accA0, (al)[0], (bh)[0], (bh)[2]); \
    MMA16816(accA1, (al)[0], (bh)[1], (bh)[3]); \
    MMA16816(accB0, (al)[1], (bh)[0], (bh)[2]); \
    MMA16816(accB1, (al)[1], (bh)[1], (bh)[3]); \
} while (0)

// ============================================================
// HMMA projection GEMM with fused fp32->bf16 split loads.
// ============================================================
#define TS 72
#define TILE_E (128*TS)

__global__ __launch_bounds__(256, 2)
void hmma_proj_kernel(const float* __restrict__ xq, const float* __restrict__ xk,
                      const float* __restrict__ xv,
                      const float* __restrict__ wq, const float* __restrict__ wk,
                      const float* __restrict__ wv,
                      float* qd, float* kd, float* vd,
                      const float* __restrict__ bq,
                      const float* __restrict__ bk,
                      const float* __restrict__ bv)
{
    __shared__ __align__(16) __nv_bfloat16 Ah[TILE_E];
    __shared__ __align__(16) __nv_bfloat16 Al[TILE_E];
    __shared__ __align__(16) __nv_bfloat16 Bh[TILE_E];
    __shared__ __align__(16) __nv_bfloat16 Bl[TILE_E];

    const int tid = threadIdx.x;
    const int lane = tid & 31, wid = tid >> 5;
    const int z = blockIdx.z;
    const int m0 = blockIdx.y * 128, n0 = blockIdx.x * 128;
    const int wm = (wid >> 1) * 32;
    const int wn = (wid & 1) * 64;

    const float* X = (z == 0) ? xq : (z == 1) ? xk : xv;
    const float* W = (z == 0) ? wq : (z == 1) ? wk : wv;
    float* dst = (z == 0) ? qd : (z == 1) ? kd : vd;
    const float* bias = (z == 0) ? bq : (z == 1) ? bk : bv;

    float acc[2][8][4];
#pragma unroll
    for (int i = 0; i < 2; i++)
#pragma unroll
        for (int j = 0; j < 8; j++)
#pragma unroll
            for (int c = 0; c < 4; c++) acc[i][j][c] = 0.f;

    const int lrow = lane & 15, lhalf = lane >> 4;
    const uint32_t sAh = smem_u32(Ah), sAl = smem_u32(Al);
    const uint32_t sBh = smem_u32(Bh), sBl = smem_u32(Bl);
    uint32_t aoffH = sAh + (uint32_t)(((wm + lrow)*TS + lhalf*8) * 2);
    uint32_t aoffL = sAl + (uint32_t)(((wm + lrow)*TS + lhalf*8) * 2);
    uint32_t boffH[4], boffL[4];
#pragma unroll
    for (int nq = 0; nq < 4; nq++) {
        boffH[nq] = sBh + (uint32_t)(((wn + nq*16 + lrow)*TS + lhalf*8) * 2);
        boffL[nq] = sBl + (uint32_t)(((wn + nq*16 + lrow)*TS + lhalf*8) * 2);
    }

    const int ldrow = tid >> 3, ldc8 = (tid & 7) << 3;

    for (int kc = 0; kc < 8; kc++) {
        __syncthreads();
#pragma unroll
        for (int it = 0; it < 4; it++) {
            int row = ldrow + it*32;
            const float* xr = X + (size_t)(m0 + row)*F_ + kc*64 + ldc8;
            const float* wr = W + (size_t)(n0 + row)*F_ + kc*64 + ldc8;
            uint4 hi, lo;
            split8(xr, hi, lo);
            *(uint4*)(Ah + row*TS + ldc8) = hi;
            *(uint4*)(Al + row*TS + ldc8) = lo;
            split8(wr, hi, lo);
            *(uint4*)(Bh + row*TS + ldc8) = hi;
            *(uint4*)(Bl + row*TS + ldc8) = lo;
        }
        __syncthreads();

#pragma unroll
        for (int kt = 0; kt < 4; kt++) {
            const uint32_t kb = kt * 32;
            uint32_t ah[2][4], al[2][4];
            LDSM4(ah[0], aoffH + kb);
            LDSM4(ah[1], aoffH + kb + 16*TS*2);
            LDSM4(al[0], aoffL + kb);
            LDSM4(al[1], aoffL + kb + 16*TS*2);
#pragma unroll
            for (int nq = 0; nq < 4; nq++) {
                uint32_t bh[4], bl[4];
                LDSM4(bh, boffH[nq] + kb);
                LDSM4(bl, boffL[nq] + kb);
                MMA_GROUP(acc[0][nq*2], acc[0][nq*2+1],
                          acc[1][nq*2], acc[1][nq*2+1],
                          ah, al, bh, bl);
            }
        }
    }

    __nv_bfloat16* sp = (z == 0) ? g_qs : g_ks;
    const int r0 = lane >> 2, c0 = (lane & 3) << 1;
#pragma unroll
    for (int mi = 0; mi < 2; mi++) {
        int mA = m0 + wm + mi*16 + r0;
        int mB = mA + 8;
        int bA = mA >> 10, lA = mA & (L_-1);
        int bB = mB >> 10, lB = mB & (L_-1);
#pragma unroll
        for (int ni = 0; ni < 8; ni++) {
            int n = n0 + wn + ni*8 + c0;
            int h = n >> 6, d = n & 63;
            float b0v = bias[n], b1v = bias[n+1];
            float vA0 = acc[mi][ni][0] + b0v, vA1 = acc[mi][ni][1] + b1v;
            float vB0 = acc[mi][ni][2] + b0v, vB1 = acc[mi][ni][3] + b1v;
            size_t rowA = (size_t)(bA*H_ + h)*L_ + lA;
            size_t rowB = (size_t)(bB*H_ + h)*L_ + lB;
            *(float2*)(dst + rowA*D_ + d) = make_float2(vA0, vA1);
            *(float2*)(dst + rowB*D_ + d) = make_float2(vB0, vB1);
            if (z < 2) {
                float hA0 = __bfloat162float(__float2bfloat16(vA0));
                float hA1 = __bfloat162float(__float2bfloat16(vA1));
                float hB0 = __bfloat162float(__float2bfloat16(vB0));
                float hB1 = __bfloat162float(__float2bfloat16(vB1));
                __nv_bfloat16* pA = sp + rowA*128 + d;
                __nv_bfloat16* pB = sp + rowB*128 + d;
                *(uint32_t*)pA        = pack_bf2(vA0, vA1);
                *(uint32_t*)(pA + 64) = pack_bf2(vA0 - hA0, vA1 - hA1);
                *(uint32_t*)pB        = pack_bf2(vB0, vB1);
                *(uint32_t*)(pB + 64) = pack_bf2(vB0 - hB0, vB1 - hB1);
            }
        }
    }
}

// ============================================================
// qk M kernel via HMMA split-bf16 (static smem, 2 CTAs/SM)
// ============================================================
__global__ __launch_bounds__(256, 2)
void qk_hmma_kernel()
{
    __shared__ __align__(16) __nv_bfloat16 Qh[TILE_E];
    __shared__ __align__(16) __nv_bfloat16 Ql[TILE_E];
    __shared__ __align__(16) __nv_bfloat16 Kh[TILE_E];
    __shared__ __align__(16) __nv_bfloat16 Kl[TILE_E];
    __shared__ float redmax[2][128];
    __shared__ float redsum[2][128];

    const int tid = threadIdx.x;
    const int lane = tid & 31, wid = tid >> 5;
    const int bh_ = blockIdx.y, q0 = blockIdx.x * 128;
    const int wm = (wid >> 1) * 32, wn = (wid & 1) * 64;

    const __nv_bfloat16* qs = g_qs + (size_t)bh_*L_*128;
    const __nv_bfloat16* ks = g_ks + (size_t)bh_*L_*128;

#pragma unroll
    for (int it = 0; it < 4; it++) {
        int idx = tid + it*256;
        int row = idx >> 3, c8 = (idx & 7) << 3;
        const __nv_bfloat16* src = qs + (size_t)(q0 + row)*128 + c8;
        *(uint4*)(Qh + row*TS + c8) = *(const uint4*)(src);
        *(uint4*)(Ql + row*TS + c8) = *(const uint4*)(src + 64);
    }

    const int lrow = lane & 15, lhalf = lane >> 4;
    const uint32_t sQh = smem_u32(Qh), sQl = smem_u32(Ql);
    const uint32_t sKh = smem_u32(Kh), sKl = smem_u32(Kl);
    uint32_t aoffH = sQh + (uint32_t)(((wm + lrow)*TS + lhalf*8) * 2);
    uint32_t aoffL = sQl + (uint32_t)(((wm + lrow)*TS + lhalf*8) * 2);
    uint32_t boffH[4], boffL[4];
#pragma unroll
    for (int nq = 0; nq < 4; nq++) {
        boffH[nq] = sKh + (uint32_t)(((wn + nq*16 + lrow)*TS + lhalf*8) * 2);
        boffL[nq] = sKl + (uint32_t)(((wn + nq*16 + lrow)*TS + lhalf*8) * 2);
    }

    float rmax_[2][2], rsum_[2][2];
#pragma unroll
    for (int i = 0; i < 2; i++)
#pragma unroll
        for (int j = 0; j < 2; j++) { rmax_[i][j] = -INF_F; rsum_[i][j] = 0.f; }

    for (int kt = 0; kt < 8; kt++) {
        __syncthreads();
#pragma unroll
        for (int it = 0; it < 4; it++) {
            int idx = tid + it*256;
            int row = idx >> 3, c8 = (idx & 7) << 3;
            const __nv_bfloat16* src = ks + (size_t)(kt*128 + row)*128 + c8;
            *(uint4*)(Kh + row*TS + c8) = *(const uint4*)(src);
            *(uint4*)(Kl + row*TS + c8) = *(const uint4*)(src + 64);
        }
        __syncthreads();

        float acc[2][8][4];
#pragma unroll
        for (int i = 0; i < 2; i++)
#pragma unroll
            for (int j = 0; j < 8; j++)
#pragma unroll
                for (int c = 0; c < 4; c++) acc[i][j][c] = 0.f;

#pragma unroll
        for (int k16 = 0; k16 < 4; k16++) {
            const uint32_t kb = k16 * 32;
            uint32_t ah[2][4], al[2][4];
            LDSM4(ah[0], aoffH + kb);
            LDSM4(ah[1], aoffH + kb + 16*TS*2);
            LDSM4(al[0], aoffL + kb);
            LDSM4(al[1], aoffL + kb + 16*TS*2);
#pragma unroll
            for (int nq = 0; nq < 4; nq++) {
                uint32_t bhf[4], blf[4];
                LDSM4(bhf, boffH[nq] + kb);
                LDSM4(blf, boffL[nq] + kb);
                MMA_GROUP(acc[0][nq*2], acc[0][nq*2+1],
                          acc[1][nq*2], acc[1][nq*2+1],
                          ah, al, bhf, blf);
            }
        }

#pragma unroll
        for (int mi = 0; mi < 2; mi++) {
            float m0 = -INF_F, m1 = -INF_F, s0 = 0.f, s1 = 0.f;
#pragma unroll
            for (int ni = 0; ni < 8; ni++) {
                m0 = fmaxf(m0, fmaxf(acc[mi][ni][0], acc[mi][ni][1]));
                s0 += acc[mi][ni][0] + acc[mi][ni][1];
                m1 = fmaxf(m1, fmaxf(acc[mi][ni][2], acc[mi][ni][3]));
                s1 += acc[mi][ni][2] + acc[mi][ni][3];
            }
            rmax_[mi][0] = fmaxf(rmax_[mi][0], m0); rsum_[mi][0] += s0;
            rmax_[mi][1] = fmaxf(rmax_[mi][1], m1); rsum_[mi][1] += s1;
        }
    }

#pragma unroll
    for (int mi = 0; mi < 2; mi++)
#pragma unroll
        for (int hf = 0; hf < 2; hf++) {
            float m = rmax_[mi][hf], s = rsum_[mi][hf];
#pragma unroll
            for (int off = 1; off <= 2; off <<= 1) {
                m = fmaxf(m, __shfl_xor_sync(0xffffffffu, m, off));
                s += __shfl_xor_sync(0xffffffffu, s, off);
            }
            rmax_[mi][hf] = m; rsum_[mi][hf] = s;
        }
    if ((lane & 3) == 0) {
        int r0 = lane >> 2;
#pragma unroll
        for (int mi = 0; mi < 2; mi++)
#pragma unroll
            for (int hf = 0; hf < 2; hf++) {
                int row = wm + mi*16 + hf*8 + r0;
                redmax[wid & 1][row] = rmax_[mi][hf];
                redsum[wid & 1][row] = rsum_[mi][hf];
            }
    }
    __syncthreads();
    if (tid < 128) {
        float m = fmaxf(redmax[0][tid], redmax[1][tid]);
        float s = redsum[0][tid] + redsum[1][tid];
        g_M[(size_t)bh_*L_ + q0 + tid] = m - s * (1.0f/L_);
    }
}

// ============================================================
// topk phase 1: per-warp top-35 of one half (512 vals) of a bh
// grid 32, 256 thr (8 warps): gw = bh*2 + half
// ============================================================
__global__ __launch_bounds__(256)
void topk_part_kernel()
{
    const int warp = threadIdx.x >> 5, lane = threadIdx.x & 31;
    const int gw = blockIdx.x * 8 + warp;
    const int bh = gw >> 1, half = gw & 1;
    const float* Mp = g_M + (size_t)bh*L_ + half*512;
    float v[16];
#pragma unroll
    for (int j = 0; j < 16; j++) v[j] = Mp[j*32 + lane];

    for (int it = 0; it < U_; it++) {
        float bv = v[0]; int bj = 0;
#pragma unroll
        for (int j = 1; j < 16; j++)
            if (v[j] > bv) { bv = v[j]; bj = j; }
        int bk = half*512 + bj*32 + lane;
#pragma unroll
        for (int off = 16; off; off >>= 1) {
            float ov = __shfl_xor_sync(0xffffffffu, bv, off);
            int   ok = __shfl_xor_sync(0xffffffffu, bk, off);
            if (ov > bv || (ov == bv && ok < bk)) { bv = ov; bk = ok; }
        }
        if (lane == 0) {
            g_cval[gw*U_ + it] = bv;
            g_cidx[gw*U_ + it] = bk;
        }
        int lk = bk - half*512;
        int cj = lk >> 5;
        bool mine = ((lk & 31) == lane);
#pragma unroll
        for (int j = 0; j < 16; j++)
            if (mine && j == cj) v[j] = -INF_F;
    }
}

// ============================================================
// topk phase 2: merge 70 candidates per bh -> top-35
// grid 16, 256 thr: warp per bh
// ============================================================
__global__ __launch_bounds__(256)
void topk_merge_kernel()
{
    const int warp = threadIdx.x >> 5, lane = threadIdx.x & 31;
    const int bh = blockIdx.x * 8 + warp;
    float cv[3]; int ci[3];
#pragma unroll
    for (int s = 0; s < 3; s++) {
        int c = lane + s*32;
        bool ok = (c < 2*U_);
        cv[s] = ok ? g_cval[bh*2*U_ + c] : -INF_F;
        ci[s] = ok ? g_cidx[bh*2*U_ + c] : 0x7fffffff;
    }

    for (int it = 0; it < U_; it++) {
        float bv = cv[0]; int bi = ci[0], bs = 0;
#pragma unroll
        for (int s = 1; s < 3; s++)
            if (cv[s] > bv || (cv[s] == bv && ci[s] < bi)) {
                bv = cv[s]; bi = ci[s]; bs = s;
            }
#pragma unroll
        for (int off = 16; off; off >>= 1) {
            float ov = __shfl_xor_sync(0xffffffffu, bv, off);
            int   oi = __shfl_xor_sync(0xffffffffu, bi, off);
            if (ov > bv || (ov == bv && oi < bi)) { bv = ov; bi = oi; }
        }
        if (lane == 0) g_idx[bh*U_ + it] = bi;
        // clear the winning candidate slot
#pragma unroll
        for (int s = 0; s < 3; s++)
            if (s == bs && ci[s] == bi && cv[s] == bv) {
                // only the true winner lane clears (idx unique)
                cv[s] = -INF_F; ci[s] = 0x7fffffff;
            }
        // broadcast winner idx and ensure exactly slots matching it clear
        int w = __shfl_sync(0xffffffffu, bi, 0);
        (void)w;
    }
}

// ============================================================
__global__ __launch_bounds__(256)
void vmean_kernel()
{
    const int bh = blockIdx.x, tid = threadIdx.x;
    const int d = tid & 63, part = tid >> 6;
    const float* vp = g_v + (size_t)bh*L_*D_;
    float acc = 0.f;
    for (int l = part*256; l < part*256 + 256; l++)
        acc += vp[(size_t)l*D_ + d];
    __shared__ float red[4][64];
    red[part][d] = acc;
    __syncthreads();
    if (tid < 64)
        g_vm[bh*64 + tid] =
            (red[0][tid] + red[1][tid] + red[2][tid] + red[3][tid]) * (1.0f/L_);
}

__global__ void zero_kernel()
{
    int t = blockIdx.x*256 + threadIdx.x;
    if (t < B_*L_) g_flag[t] = 0;
    if (t < B_)    g_cnt[t]  = 0;
}

__global__ void compact_kernel()
{
    int t = blockIdx.x*256 + threadIdx.x;
    if (t >= BH_*U_) return;
    int bh = t / U_;
    int b  = bh >> 3;
    int row = g_idx[t];
    if (atomicExch(&g_flag[b*L_ + row], 1) == 0) {
        int p = atomicAdd(&g_cnt[b], 1);
        g_rows[b*L_ + p] = row;
    }
}

// grid (B_, 24): 16 rows per block
__global__ __launch_bounds__(256)
void x2init_kernel()
{
    const int b = blockIdx.x, t = blockIdx.y, tid = threadIdx.x;
    __shared__ float vms[F_];
    for (int f = tid; f < F_; f += 256)
        vms[f] = g_vm[(b*H_ + (f >> 6))*64 + (f & 63)];
    __syncthreads();
    const int cnt = g_cnt[b];
    int lo = t*16, hiR = lo + 16; if (hiR > cnt) hiR = cnt;
    for (int ri = lo; ri < hiR; ri++) {
        int l = g_rows[b*L_ + ri];
        float* p = g_x2 + ((size_t)b*L_ + l)*F_;
        p[tid]       = vms[tid];
        p[tid + 256] = vms[tid + 256];
    }
}

// ============================================================
__global__ __launch_bounds__(256)
void sp_scores_kernel(const int* __restrict__ mask)
{
    __shared__ float qs[U_][64];
    __shared__ float Ks[128][68];
    __shared__ int   sidx[U_];
    const int bh = blockIdx.x, tid = threadIdx.x;
    const int b = bh >> 3;
    const int kt0 = blockIdx.y << 7;
    const float* qp = g_q + (size_t)bh*L_*D_;
    const float* kp = g_k + (size_t)bh*L_*D_;
    float* scp = g_sc + (size_t)bh*U_*L_;
    const int* mrow = mask + b*L_;

    if (tid < U_) sidx[tid] = g_idx[bh*U_ + tid];
    __syncthreads();
    for (int i = tid; i < U_*16; i += 256) {
        int u = i >> 4, dc = (i & 15) << 2;
        *(float4*)&qs[u][dc] = *(const float4*)(qp + (size_t)sidx[u]*D_ + dc);
    }
    for (int i = tid; i < 128*16; i += 256) {
        int k = i >> 4, dc = (i & 15) << 2;
        *(float4*)&Ks[k][dc] = *(const float4*)(kp + (size_t)(kt0 + k)*D_ + dc);
    }
    __syncthreads();

    for (int p = tid; p < U_*128; p += 256) {
        int u = p >> 7, kk = p & 127;
        float s = 0.f;
#pragma unroll
        for (int dc = 0; dc < 64; dc += 4) {
            float4 a = *(const float4*)&qs[u][dc];
            float4 c = *(const float4*)&Ks[kk][dc];
            s += a.x*c.x + a.y*c.y + a.z*c.z + a.w*c.w;
        }
        int k = kt0 + kk;
        s *= 0.125f;
        if (mrow[k] == 0) s = -INF_F;
        scp[(size_t)u*L_ + k] = s;
    }
}

__global__ __launch_bounds__(256)
void sp_softmax_kernel()
{
    const int bh = blockIdx.x, tid = threadIdx.x;
    float* scp = g_sc + (size_t)bh*U_*L_;
    const int wid = tid >> 5, lane = tid & 31;
    for (int u = wid; u < U_; u += 8) {
        float mx = -INF_F;
        for (int k = lane; k < L_; k += 32)
            mx = fmaxf(mx, scp[(size_t)u*L_ + k]);
#pragma unroll
        for (int off = 16; off; off >>= 1)
            mx = fmaxf(mx, __shfl_xor_sync(0xffffffffu, mx, off));
        float sm = 0.f;
        for (int k = lane; k < L_; k += 32) {
            float s = scp[(size_t)u*L_ + k];
            sm += (s == -INF_F) ? 0.f : expf(s - mx);
        }
#pragma unroll
        for (int off = 16; off; off >>= 1)
            sm += __shfl_xor_sync(0xffffffffu, sm, off);
        float inv = (sm > 0.f) ? 1.0f / sm : 0.f;
        for (int k = lane; k < L_; k += 32) {
            float s = scp[(size_t)u*L_ + k];
            float pv = (s == -INF_F || mx == -INF_F) ? 0.f : expf(s - mx) * inv;
            scp[(size_t)u*L_ + k] = pv;
        }
    }
}

// ============================================================
// sp_ctx split-k: grid (BH_, 4); block covers 256 keys; writes
// deterministic partials to g_ctxp[kp][bh][u][d]
// ============================================================
__global__ __launch_bounds__(256)
void sp_ctx_part_kernel()
{
    __shared__ float ps[U_][64];
    __shared__ float cb[U_][64];
    const int bh = blockIdx.x, kp = blockIdx.y, tid = threadIdx.x;
    const float* vp = g_v + (size_t)bh*L_*D_;
    const float* scp = g_sc + (size_t)bh*U_*L_;
    const int d = tid & 63, part = tid >> 6;

    float acc[U_];
#pragma unroll
    for (int u = 0; u < U_; u++) acc[u] = 0.f;

    for (int kt = 0; kt < 4; kt++) {
        const int k0 = kp*256 + kt*64;
        __syncthreads();
        for (int i = tid; i < U_*64; i += 256) {
            int u = i >> 6, kk = i & 63;
            ps[u][kk] = scp[(size_t)u*L_ + k0 + kk];
        }
        __syncthreads();
        for (int kk = part*16; kk < part*16 + 16; kk++) {
            float v = vp[(size_t)(k0 + kk)*D_ + d];
#pragma unroll
            for (int u = 0; u < U_; u++)
                acc[u] += ps[u][kk] * v;
        }
    }
    __syncthreads();
    for (int p2 = 0; p2 < 4; p2++) {
        if (part == p2) {
#pragma unroll
            for (int u = 0; u < U_; u++) {
                if (p2 == 0) cb[u][d] = acc[u];
                else         cb[u][d] += acc[u];
            }
        }
        __syncthreads();
    }
    float* dst = g_ctxp + (((size_t)kp*BH_ + bh)*U_)*64;
    for (int i = tid; i < U_*64; i += 256)
        dst[i] = cb[i >> 6][i & 63];
}

// sum 4 partials and scatter into x2; grid BH_
__global__ __launch_bounds__(256)
void sp_scatter_kernel()
{
    __shared__ int sidx[U_];
    const int bh = blockIdx.x, tid = threadIdx.x;
    const int b = bh >> 3, h = bh & 7;
    if (tid < U_) sidx[tid] = g_idx[bh*U_ + tid];
    __syncthreads();
    float* x2 = g_x2 + (size_t)b*L_*F_ + h*D_;
    for (int i = tid; i < U_*64; i += 256) {
        int u = i >> 6, dd = i & 63;
        size_t off = (((size_t)bh)*U_ + u)*64 + dd;
        float s = g_ctxp[off]
                + g_ctxp[off + (size_t)BH_*U_*64]
                + g_ctxp[off + 2ULL*BH_*U_*64]
                + g_ctxp[off + 3ULL*BH_*U_*64];
        x2[(size_t)sidx[u]*F_ + dd] = s;
    }
}

// ============================================================
__global__ __launch_bounds__(256)
void mean_out_kernel(const float* __restrict__ Wo, const float* __restrict__ bo)
{
    const int b = blockIdx.x, t = blockIdx.y, tid = threadIdx.x;
    __shared__ float vms[F_];
    __shared__ float red[128];
    for (int f = tid; f < F_; f += 256)
        vms[f] = g_vm[(b*H_ + (f >> 6))*64 + (f & 63)];
    __syncthreads();
    const int half = tid >> 7, nloc = tid & 127;
    const int n = t*128 + nloc;
    const float* w = Wo + (size_t)n*F_ + half*256;
    const float* vv = vms + half*256;
    float s = 0.f;
#pragma unroll 8
    for (int f = 0; f < 256; f += 4) {
        float4 wv = *(const float4*)(w + f);
        s += vv[f]*wv.x + vv[f+1]*wv.y + vv[f+2]*wv.z + vv[f+3]*wv.w;
    }
    if (half) red[nloc] = s;
    __syncthreads();
    if (!half) g_om[b*F_ + n] = s + red[nloc] + bo[n];
}

__global__ __launch_bounds__(256)
void bcast_kernel(float* __restrict__ out)
{
    const int b = blockIdx.x, l0 = blockIdx.y << 3, tid = threadIdx.x;
    __shared__ float om[F_];
    for (int f = tid; f < F_; f += 256) om[f] = g_om[b*F_ + f];
    __syncthreads();
    float2 v = *(const float2*)&om[tid*2];
    float* base = out + ((size_t)b*L_ + l0)*F_;
#pragma unroll
    for (int rr = 0; rr < 8; rr++)
        *(float2*)(base + (size_t)rr*F_ + tid*2) = v;
}

// ============================================================
__global__ __launch_bounds__(256, 2)
void gemm_rows_kernel(const float* __restrict__ W,
                      const float* __restrict__ bias,
                      float* __restrict__ out)
{
    const int b = blockIdx.y / 3;
    const int t = blockIdx.y % 3;
    const int cnt = g_cnt[b];
    if (t * 128 >= cnt) return;

    __shared__ __align__(16) float As[2][16][132];
    __shared__ __align__(16) float Bs[2][16][132];
    __shared__ int rows_s[128];

    const int tid = threadIdx.x;
    if (tid < 128) {
        int gi = t*128 + tid;
        rows_s[tid] = (gi < cnt) ? g_rows[b*L_ + gi] : g_rows[b*L_];
    }
    __syncthreads();

    const float* X = g_x2 + (size_t)b*L_*F_;
    const int tx = tid & 15, ty = tid >> 4;
    const int n0 = blockIdx.x * 128;
    const int r  = tid >> 2;
    const int kc = (tid & 3) << 2;
    const int mo = r << 1;
    const int l0r = rows_s[r], l1r = rows_s[r + 64];

    u64 acc[4][8];
#pragma unroll
    for (int i = 0; i < 4; i++)
#pragma unroll
        for (int j = 0; j < 8; j++) acc[i][j] = 0ULL;

    float4 ra0, ra1, rb0, rb1;
    ra0 = *(const float4*)(X + (size_t)l0r*F_ + kc);
    ra1 = *(const float4*)(X + (size_t)l1r*F_ + kc);
    rb0 = *(const float4*)(W + (size_t)(n0 + r)*F_ + kc);
    rb1 = *(const float4*)(W + (size_t)(n0 + r + 64)*F_ + kc);

#define GSTORE(bsel) do { \
    As[bsel][kc+0][mo]   = ra0.x; As[bsel][kc+1][mo]   = ra0.y; \
    As[bsel][kc+2][mo]   = ra0.z; As[bsel][kc+3][mo]   = ra0.w; \
    As[bsel][kc+0][mo+1] = ra1.x; As[bsel][kc+1][mo+1] = ra1.y; \
    As[bsel][kc+2][mo+1] = ra1.z; As[bsel][kc+3][mo+1] = ra1.w; \
    Bs[bsel][kc+0][r]    = rb0.x; Bs[bsel][kc+1][r]    = rb0.y; \
    Bs[bsel][kc+2][r]    = rb0.z; Bs[bsel][kc+3][r]    = rb0.w; \
    Bs[bsel][kc+0][r+64] = rb1.x; Bs[bsel][kc+1][r+64] = rb1.y; \
    Bs[bsel][kc+2][r+64] = rb1.z; Bs[bsel][kc+3][r+64] = rb1.w; } while(0)

    GSTORE(0);
    __syncthreads();

    for (int c = 0; c < 32; c++) {
        if (c < 31) {
            int kb = (c + 1) << 4;
            ra0 = *(const float4*)(X + (size_t)l0r*F_ + kb + kc);
            ra1 = *(const float4*)(X + (size_t)l1r*F_ + kb + kc);
            rb0 = *(const float4*)(W + (size_t)(n0 + r)*F_ + kb + kc);
            rb1 = *(const float4*)(W + (size_t)(n0 + r + 64)*F_ + kb + kc);
        }
        const int bsel = c & 1;
#pragma unroll
        for (int kk = 0; kk < 16; kk++) {
            ulonglong2 a01 = *(const ulonglong2*)&As[bsel][kk][ty << 3];
            ulonglong2 a23 = *(const ulonglong2*)&As[bsel][kk][(ty << 3) + 4];
            float4 b0 = *(const float4*)&Bs[bsel][kk][tx << 3];
            float4 b1 = *(const float4*)&Bs[bsel][kk][(tx << 3) + 4];
            u64 av[4] = {a01.x, a01.y, a23.x, a23.y};
            u64 bv[8] = {dup2(b0.x), dup2(b0.y), dup2(b0.z), dup2(b0.w),
                         dup2(b1.x), dup2(b1.y), dup2(b1.z), dup2(b1.w)};
#pragma unroll
            for (int i = 0; i < 4; i++)
#pragma unroll
                for (int j = 0; j < 8; j++)
                    fma2(acc[i][j], av[i], bv[j]);
        }
        if (c < 31) GSTORE((c + 1) & 1);
        __syncthreads();
    }
#undef GSTORE

    const int nb = n0 + (tx << 3);
    float bb[8];
#pragma unroll
    for (int j = 0; j < 8; j++) bb[j] = bias[nb + j];

#pragma unroll
    for (int i = 0; i < 4; i++) {
        float lo[8], hi[8];
#pragma unroll
        for (int j = 0; j < 8; j++) {
            float2 tt = unpk(acc[i][j]);
            lo[j] = tt.x + bb[j];
            hi[j] = tt.y + bb[j];
        }
        {
            int l = rows_s[(ty << 2) + i];
            float* p = out + ((size_t)b*L_ + l)*F_ + nb;
            *(float4*)p     = make_float4(lo[0], lo[1], lo[2], lo[3]);
            *(float4*)(p+4) = make_float4(lo[4], lo[5], lo[6], lo[7]);
        }
        {
            int l = rows_s[(ty << 2) + i + 64];
            float* p = out + ((size_t)b*L_ + l)*F_ + nb;
            *(float4*)p     = make_float4(hi[0], hi[1], hi[2], hi[3]);
            *(float4*)(p+4) = make_float4(hi[4], hi[5], hi[6], hi[7]);
        }
    }
}

// ============================================================
extern "C" void kernel_launch(void* const* d_in, const int* in_sizes, int n_in,
                              void* d_out, int out_size)
{
    const float* query = (const float*)d_in[0];
    const float* key   = (const float*)d_in[1];
    const float* value = (const float*)d_in[2];
    const int*   mask  = (const int*)  d_in[3];
    const float* Wq = (const float*)d_in[4];
    const float* bq = (const float*)d_in[5];
    const float* Wk = (const float*)d_in[6];
    const float* bk = (const float*)d_in[7];
    const float* Wv = (const float*)d_in[8];
    const float* bv = (const float*)d_in[9];
    const float* Wo = (const float*)d_in[10];
    const float* bo = (const float*)d_in[11];
    float* out = (float*)d_out;

    float *qd, *kd, *vd;
    cudaGetSymbolAddress((void**)&qd, g_q);
    cudaGetSymbolAddress((void**)&kd, g_k);
    cudaGetSymbolAddress((void**)&vd, g_v);

    zero_kernel<<<64, 256>>>();

    hmma_proj_kernel<<<dim3(F_/128, ML_/128, 3), 256>>>(
        query, key, value, Wq, Wk, Wv, qd, kd, vd, bq, bk, bv);

    qk_hmma_kernel<<<dim3(L_/128, BH_), 256>>>();

    topk_part_kernel<<<32, 256>>>();
    topk_merge_kernel<<<16, 256>>>();
    vmean_kernel<<<BH_, 256>>>();
    compact_kernel<<<(BH_*U_ + 255)/256, 256>>>();
    x2init_kernel<<<dim3(B_, 24), 256>>>();

    sp_scores_kernel<<<dim3(BH_, 8), 256>>>(mask);
    sp_softmax_kernel<<<BH_, 256>>>();
    sp_ctx_part_kernel<<<dim3(BH_, 4), 256>>>();
    sp_scatter_kernel<<<BH_, 256>>>();

    mean_out_kernel<<<dim3(B_, 4), 256>>>(Wo, bo);
    bcast_kernel<<<dim3(B_, L_/8), 256>>>(out);
    gemm_rows_kernel<<<dim3(F_/128, B_*3), 256>>>(Wo, bo, out);
}

// round 16
// speedup vs baseline: 1.2026x; 1.0065x over previous
#include <cuda_runtime.h>
#include <cuda_bf16.h>
#include <cstdint>

typedef unsigned long long u64;

#define B_  16
#define L_  1024
#define F_  512
#define H_  8
#define D_  64
#define U_  35
#define BH_ (B_*H_)
#define ML_ (B_*L_)

#define INF_F __int_as_float(0x7f800000)

// -------- device scratch --------
__device__ float g_q[(size_t)BH_*L_*D_];
__device__ float g_k[(size_t)BH_*L_*D_];
__device__ float g_v[(size_t)BH_*L_*D_];
__device__ float g_M[(size_t)BH_*L_];
__device__ int   g_idx[BH_*U_];
__device__ float g_x2[(size_t)ML_*F_];
__device__ float g_sc[(size_t)BH_*U_*L_];
__device__ float g_vm[BH_*D_];
__device__ float g_om[B_*F_];
__device__ int   g_flag[B_*L_];
__device__ int   g_cnt[B_];
__device__ int   g_rows[B_*L_];
__device__ __nv_bfloat16 g_qs[(size_t)BH_*L_*128];  // q split [hi(64)|lo(64)]
__device__ __nv_bfloat16 g_ks[(size_t)BH_*L_*128];  // k split
__device__ float g_cval[BH_*4*U_];                   // topk phase-1 candidates
__device__ int   g_cidx[BH_*4*U_];
__device__ float g_ctxp[4ULL*BH_*U_*64];             // sp_ctx partials

// -------- f32x2 helpers --------
__device__ __forceinline__ void fma2(u64 &acc, u64 a, u64 b) {
    asm("fma.rn.f32x2 %0, %1, %2, %0;" : "+l"(acc) : "l"(a), "l"(b));
}
__device__ __forceinline__ u64 dup2(float v) {
    u64 r; asm("mov.b64 %0, {%1, %1};" : "=l"(r) : "f"(v)); return r;
}
__device__ __forceinline__ float2 unpk(u64 v) {
    float2 r; asm("mov.b64 {%0, %1}, %2;" : "=f"(r.x), "=f"(r.y) : "l"(v)); return r;
}

// -------- mma.sync helpers (baseline PTX, sm_80+) --------
__device__ __forceinline__ uint32_t smem_u32(const void* p) {
    uint32_t a;
    asm("{ .reg .u64 t; cvta.to.shared.u64 t, %1; cvt.u32.u64 %0, t; }" : "=r"(a) : "l"(p));
    return a;
}
#define LDSM4(r, addr) \
    asm volatile("ldmatrix.sync.aligned.m8n8.x4.shared.b16 {%0,%1,%2,%3}, [%4];" \
        : "=r"((r)[0]), "=r"((r)[1]), "=r"((r)[2]), "=r"((r)[3]) : "r"(addr))
#define MMA16816(c, a, b0v, b1v) \
    asm("mma.sync.aligned.m16n8k16.row.col.f32.bf16.bf16.f32 " \
        "{%0,%1,%2,%3}, {%4,%5,%6,%7}, {%8,%9}, {%0,%1,%2,%3};" \
        : "+f"((c)[0]), "+f"((c)[1]), "+f"((c)[2]), "+f"((c)[3]) \
        : "r"((a)[0]), "r"((a)[1]), "r"((a)[2]), "r"((a)[3]), "r"(b0v), "r"(b1v))

__device__ __forceinline__ uint32_t pack_bf2(float x, float y) {
    __nv_bfloat162 t;
    t.x = __float2bfloat16(x);
    t.y = __float2bfloat16(y);
    return *(uint32_t*)&t;
}

// split 8 consecutive fp32 into uint4 of bf16-hi and uint4 of bf16-lo
__device__ __forceinline__ void split8(const float* __restrict__ p,
                                       uint4 &hi, uint4 &lo) {
    float4 a = *(const float4*)p;
    float4 b = *(const float4*)(p + 4);
    float v[8] = {a.x, a.y, a.z, a.w, b.x, b.y, b.z, b.w};
    uint32_t hw[4], lw[4];
#pragma unroll
    for (int i = 0; i < 4; i++) {
        float e0 = v[2*i], e1 = v[2*i+1];
        __nv_bfloat16 h0 = __float2bfloat16(e0);
        __nv_bfloat16 h1 = __float2bfloat16(e1);
        __nv_bfloat162 hp; hp.x = h0; hp.y = h1;
        hw[i] = *(uint32_t*)&hp;
        lw[i] = pack_bf2(e0 - __bfloat162float(h0), e1 - __bfloat162float(h1));
    }
    hi = make_uint4(hw[0], hw[1], hw[2], hw[3]);
    lo = make_uint4(lw[0], lw[1], lw[2], lw[3]);
}

// term-major split MMA block (gap-4 chains)
#define MMA_GROUP(accA0, accA1, accB0, accB1, ah, al, bh, bl) do { \
    MMA16816(accA0, (ah)[0], (bh)[0], (bh)[2]); \
    MMA16816(accA1, (ah)[0], (bh)[1], (bh)[3]); \
    MMA16816(accB0, (ah)[1], (bh)[0], (bh)[2]); \
    MMA16816(accB1, (ah)[1], (bh)[1], (bh)[3]); \
    MMA16816(accA0, (ah)[0], (bl)[0], (bl)[2]); \
    MMA16816(accA1, (ah)[0], (bl)[1], (bl)[3]); \
    MMA16816(accB0, (ah)[1], (bl)[0], (bl)[2]); \
    MMA16816(accB1, (ah)[1], (bl)[1], (bl)[3]); \
    MMA16816(accA0, (al)[0], (bh)[0], (bh)[2]); \
    MMA16816(accA1, (al)[0], (bh)[1], (bh)[3]); \
    MMA16816(accB0, (al)[1], (bh)[0], (bh)[2]); \
    MMA16816(accB1, (al)[1], (bh)[1], (bh)[3]); \
} while (0)

// ============================================================
// HMMA projection GEMM with fused fp32->bf16 split loads.
// ============================================================
#define TS 72
#define TILE_E (128*TS)

__global__ __launch_bounds__(256, 2)
void hmma_proj_kernel(const float* __restrict__ xq, const float* __restrict__ xk,
                      const float* __restrict__ xv,
                      const float* __restrict__ wq, const float* __restrict__ wk,
                      const float* __restrict__ wv,
                      float* qd, float* kd, float* vd,
                      const float* __restrict__ bq,
                      const float* __restrict__ bk,
                      const float* __restrict__ bv)
{
    __shared__ __align__(16) __nv_bfloat16 Ah[TILE_E];
    __shared__ __align__(16) __nv_bfloat16 Al[TILE_E];
    __shared__ __align__(16) __nv_bfloat16 Bh[TILE_E];
    __shared__ __align__(16) __nv_bfloat16 Bl[TILE_E];

    const int tid = threadIdx.x;
    const int lane = tid & 31, wid = tid >> 5;
    const int z = blockIdx.z;
    const int m0 = blockIdx.y * 128, n0 = blockIdx.x * 128;
    const int wm = (wid >> 1) * 32;
    const int wn = (wid & 1) * 64;

    const float* X = (z == 0) ? xq : (z == 1) ? xk : xv;
    const float* W = (z == 0) ? wq : (z == 1) ? wk : wv;
    float* dst = (z == 0) ? qd : (z == 1) ? kd : vd;
    const float* bias = (z == 0) ? bq : (z == 1) ? bk : bv;

    float acc[2][8][4];
#pragma unroll
    for (int i = 0; i < 2; i++)
#pragma unroll
        for (int j = 0; j < 8; j++)
#pragma unroll
            for (int c = 0; c < 4; c++) acc[i][j][c] = 0.f;

    const int lrow = lane & 15, lhalf = lane >> 4;
    const uint32_t sAh = smem_u32(Ah), sAl = smem_u32(Al);
    const uint32_t sBh = smem_u32(Bh), sBl = smem_u32(Bl);
    uint32_t aoffH = sAh + (uint32_t)(((wm + lrow)*TS + lhalf*8) * 2);
    uint32_t aoffL = sAl + (uint32_t)(((wm + lrow)*TS + lhalf*8) * 2);
    uint32_t boffH[4], boffL[4];
#pragma unroll
    for (int nq = 0; nq < 4; nq++) {
        boffH[nq] = sBh + (uint32_t)(((wn + nq*16 + lrow)*TS + lhalf*8) * 2);
        boffL[nq] = sBl + (uint32_t)(((wn + nq*16 + lrow)*TS + lhalf*8) * 2);
    }

    const int ldrow = tid >> 3, ldc8 = (tid & 7) << 3;

    for (int kc = 0; kc < 8; kc++) {
        __syncthreads();
#pragma unroll
        for (int it = 0; it < 4; it++) {
            int row = ldrow + it*32;
            const float* xr = X + (size_t)(m0 + row)*F_ + kc*64 + ldc8;
            const float* wr = W + (size_t)(n0 + row)*F_ + kc*64 + ldc8;
            uint4 hi, lo;
            split8(xr, hi, lo);
            *(uint4*)(Ah + row*TS + ldc8) = hi;
            *(uint4*)(Al + row*TS + ldc8) = lo;
            split8(wr, hi, lo);
            *(uint4*)(Bh + row*TS + ldc8) = hi;
            *(uint4*)(Bl + row*TS + ldc8) = lo;
        }
        __syncthreads();

#pragma unroll
        for (int kt = 0; kt < 4; kt++) {
            const uint32_t kb = kt * 32;
            uint32_t ah[2][4], al[2][4];
            LDSM4(ah[0], aoffH + kb);
            LDSM4(ah[1], aoffH + kb + 16*TS*2);
            LDSM4(al[0], aoffL + kb);
            LDSM4(al[1], aoffL + kb + 16*TS*2);
#pragma unroll
            for (int nq = 0; nq < 4; nq++) {
                uint32_t bh[4], bl[4];
                LDSM4(bh, boffH[nq] + kb);
                LDSM4(bl, boffL[nq] + kb);
                MMA_GROUP(acc[0][nq*2], acc[0][nq*2+1],
                          acc[1][nq*2], acc[1][nq*2+1],
                          ah, al, bh, bl);
            }
        }
    }

    __nv_bfloat16* sp = (z == 0) ? g_qs : g_ks;
    const int r0 = lane >> 2, c0 = (lane & 3) << 1;
#pragma unroll
    for (int mi = 0; mi < 2; mi++) {
        int mA = m0 + wm + mi*16 + r0;
        int mB = mA + 8;
        int bA = mA >> 10, lA = mA & (L_-1);
        int bB = mB >> 10, lB = mB & (L_-1);
#pragma unroll
        for (int ni = 0; ni < 8; ni++) {
            int n = n0 + wn + ni*8 + c0;
            int h = n >> 6, d = n & 63;
            float b0v = bias[n], b1v = bias[n+1];
            float vA0 = acc[mi][ni][0] + b0v, vA1 = acc[mi][ni][1] + b1v;
            float vB0 = acc[mi][ni][2] + b0v, vB1 = acc[mi][ni][3] + b1v;
            size_t rowA = (size_t)(bA*H_ + h)*L_ + lA;
            size_t rowB = (size_t)(bB*H_ + h)*L_ + lB;
            *(float2*)(dst + rowA*D_ + d) = make_float2(vA0, vA1);
            *(float2*)(dst + rowB*D_ + d) = make_float2(vB0, vB1);
            if (z < 2) {
                float hA0 = __bfloat162float(__float2bfloat16(vA0));
                float hA1 = __bfloat162float(__float2bfloat16(vA1));
                float hB0 = __bfloat162float(__float2bfloat16(vB0));
                float hB1 = __bfloat162float(__float2bfloat16(vB1));
                __nv_bfloat16* pA = sp + rowA*128 + d;
                __nv_bfloat16* pB = sp + rowB*128 + d;
                *(uint32_t*)pA        = pack_bf2(vA0, vA1);
                *(uint32_t*)(pA + 64) = pack_bf2(vA0 - hA0, vA1 - hA1);
                *(uint32_t*)pB        = pack_bf2(vB0, vB1);
                *(uint32_t*)(pB + 64) = pack_bf2(vB0 - hB0, vB1 - hB1);
            }
        }
    }
}

// ============================================================
// qk M kernel via HMMA split-bf16 (static smem, 2 CTAs/SM)
// ============================================================
__global__ __launch_bounds__(256, 2)
void qk_hmma_kernel()
{
    __shared__ __align__(16) __nv_bfloat16 Qh[TILE_E];
    __shared__ __align__(16) __nv_bfloat16 Ql[TILE_E];
    __shared__ __align__(16) __nv_bfloat16 Kh[TILE_E];
    __shared__ __align__(16) __nv_bfloat16 Kl[TILE_E];
    __shared__ float redmax[2][128];
    __shared__ float redsum[2][128];

    const int tid = threadIdx.x;
    const int lane = tid & 31, wid = tid >> 5;
    const int bh_ = blockIdx.y, q0 = blockIdx.x * 128;
    const int wm = (wid >> 1) * 32, wn = (wid & 1) * 64;

    const __nv_bfloat16* qs = g_qs + (size_t)bh_*L_*128;
    const __nv_bfloat16* ks = g_ks + (size_t)bh_*L_*128;

#pragma unroll
    for (int it = 0; it < 4; it++) {
        int idx = tid + it*256;
        int row = idx >> 3, c8 = (idx & 7) << 3;
        const __nv_bfloat16* src = qs + (size_t)(q0 + row)*128 + c8;
        *(uint4*)(Qh + row*TS + c8) = *(const uint4*)(src);
        *(uint4*)(Ql + row*TS + c8) = *(const uint4*)(src + 64);
    }

    const int lrow = lane & 15, lhalf = lane >> 4;
    const uint32_t sQh = smem_u32(Qh), sQl = smem_u32(Ql);
    const uint32_t sKh = smem_u32(Kh), sKl = smem_u32(Kl);
    uint32_t aoffH = sQh + (uint32_t)(((wm + lrow)*TS + lhalf*8) * 2);
    uint32_t aoffL = sQl + (uint32_t)(((wm + lrow)*TS + lhalf*8) * 2);
    uint32_t boffH[4], boffL[4];
#pragma unroll
    for (int nq = 0; nq < 4; nq++) {
        boffH[nq] = sKh + (uint32_t)(((wn + nq*16 + lrow)*TS + lhalf*8) * 2);
        boffL[nq] = sKl + (uint32_t)(((wn + nq*16 + lrow)*TS + lhalf*8) * 2);
    }

    float rmax_[2][2], rsum_[2][2];
#pragma unroll
    for (int i = 0; i < 2; i++)
#pragma unroll
        for (int j = 0; j < 2; j++) { rmax_[i][j] = -INF_F; rsum_[i][j] = 0.f; }

    for (int kt = 0; kt < 8; kt++) {
        __syncthreads();
#pragma unroll
        for (int it = 0; it < 4; it++) {
            int idx = tid + it*256;
            int row = idx >> 3, c8 = (idx & 7) << 3;
            const __nv_bfloat16* src = ks + (size_t)(kt*128 + row)*128 + c8;
            *(uint4*)(Kh + row*TS + c8) = *(const uint4*)(src);
            *(uint4*)(Kl + row*TS + c8) = *(const uint4*)(src + 64);
        }
        __syncthreads();

        float acc[2][8][4];
#pragma unroll
        for (int i = 0; i < 2; i++)
#pragma unroll
            for (int j = 0; j < 8; j++)
#pragma unroll
                for (int c = 0; c < 4; c++) acc[i][j][c] = 0.f;

#pragma unroll
        for (int k16 = 0; k16 < 4; k16++) {
            const uint32_t kb = k16 * 32;
            uint32_t ah[2][4], al[2][4];
            LDSM4(ah[0], aoffH + kb);
            LDSM4(ah[1], aoffH + kb + 16*TS*2);
            LDSM4(al[0], aoffL + kb);
            LDSM4(al[1], aoffL + kb + 16*TS*2);
#pragma unroll
            for (int nq = 0; nq < 4; nq++) {
                uint32_t bhf[4], blf[4];
                LDSM4(bhf, boffH[nq] + kb);
                LDSM4(blf, boffL[nq] + kb);
                MMA_GROUP(acc[0][nq*2], acc[0][nq*2+1],
                          acc[1][nq*2], acc[1][nq*2+1],
                          ah, al, bhf, blf);
            }
        }

#pragma unroll
        for (int mi = 0; mi < 2; mi++) {
            float m0 = -INF_F, m1 = -INF_F, s0 = 0.f, s1 = 0.f;
#pragma unroll
            for (int ni = 0; ni < 8; ni++) {
                m0 = fmaxf(m0, fmaxf(acc[mi][ni][0], acc[mi][ni][1]));
                s0 += acc[mi][ni][0] + acc[mi][ni][1];
                m1 = fmaxf(m1, fmaxf(acc[mi][ni][2], acc[mi][ni][3]));
                s1 += acc[mi][ni][2] + acc[mi][ni][3];
            }
            rmax_[mi][0] = fmaxf(rmax_[mi][0], m0); rsum_[mi][0] += s0;
            rmax_[mi][1] = fmaxf(rmax_[mi][1], m1); rsum_[mi][1] += s1;
        }
    }

#pragma unroll
    for (int mi = 0; mi < 2; mi++)
#pragma unroll
        for (int hf = 0; hf < 2; hf++) {
            float m = rmax_[mi][hf], s = rsum_[mi][hf];
#pragma unroll
            for (int off = 1; off <= 2; off <<= 1) {
                m = fmaxf(m, __shfl_xor_sync(0xffffffffu, m, off));
                s += __shfl_xor_sync(0xffffffffu, s, off);
            }
            rmax_[mi][hf] = m; rsum_[mi][hf] = s;
        }
    if ((lane & 3) == 0) {
        int r0 = lane >> 2;
#pragma unroll
        for (int mi = 0; mi < 2; mi++)
#pragma unroll
            for (int hf = 0; hf < 2; hf++) {
                int row = wm + mi*16 + hf*8 + r0;
                redmax[wid & 1][row] = rmax_[mi][hf];
                redsum[wid & 1][row] = rsum_[mi][hf];
            }
    }
    __syncthreads();
    if (tid < 128) {
        float m = fmaxf(redmax[0][tid], redmax[1][tid]);
        float s = redsum[0][tid] + redsum[1][tid];
        g_M[(size_t)bh_*L_ + q0 + tid] = m - s * (1.0f/L_);
    }
}

// ============================================================
// topk phase 1: per-warp top-35 of one quarter (256 vals)
// grid 64, 256 thr (8 warps): gw = bh*4 + quarter
// ============================================================
__global__ __launch_bounds__(256)
void topk_part_kernel()
{
    const int warp = threadIdx.x >> 5, lane = threadIdx.x & 31;
    const int gw = blockIdx.x * 8 + warp;
    const int bh = gw >> 2, qt = gw & 3;
    const float* Mp = g_M + (size_t)bh*L_ + qt*256;
    float v[8];
#pragma unroll
    for (int j = 0; j < 8; j++) v[j] = Mp[j*32 + lane];

    for (int it = 0; it < U_; it++) {
        float bv = v[0]; int bj = 0;
#pragma unroll
        for (int j = 1; j < 8; j++)
            if (v[j] > bv) { bv = v[j]; bj = j; }
        int bk = qt*256 + bj*32 + lane;
#pragma unroll
        for (int off = 16; off; off >>= 1) {
            float ov = __shfl_xor_sync(0xffffffffu, bv, off);
            int   ok = __shfl_xor_sync(0xffffffffu, bk, off);
            if (ov > bv || (ov == bv && ok < bk)) { bv = ov; bk = ok; }
        }
        if (lane == 0) {
            g_cval[gw*U_ + it] = bv;
            g_cidx[gw*U_ + it] = bk;
        }
        int lk = bk - qt*256;
        int cj = lk >> 5;
        bool mine = ((lk & 31) == lane);
#pragma unroll
        for (int j = 0; j < 8; j++)
            if (mine && j == cj) v[j] = -INF_F;
    }
}

// ============================================================
// topk phase 2: merge 140 candidates per bh -> top-35, then
// fused selected-row compaction. Winners parked in 2 register
// slots (35 > 32 lanes): it<32 -> lane it, it>=32 -> lane it-32.
// grid 16, 256 thr: warp per bh
// ============================================================
__global__ __launch_bounds__(256)
void topk_merge_kernel()
{
    const int warp = threadIdx.x >> 5, lane = threadIdx.x & 31;
    const int bh = blockIdx.x * 8 + warp;
    const int b = bh >> 3;
    float cv[5]; int ci[5];
#pragma unroll
    for (int s = 0; s < 5; s++) {
        int c = lane + s*32;
        bool ok = (c < 4*U_);
        cv[s] = ok ? g_cval[bh*4*U_ + c] : -INF_F;
        ci[s] = ok ? g_cidx[bh*4*U_ + c] : 0x7fffffff;
    }

    int myrow0 = -1, myrow1 = -1;
    for (int it = 0; it < U_; it++) {
        float bv = cv[0]; int bi = ci[0], bs = 0;
#pragma unroll
        for (int s = 1; s < 5; s++)
            if (cv[s] > bv || (cv[s] == bv && ci[s] < bi)) {
                bv = cv[s]; bi = ci[s]; bs = s;
            }
#pragma unroll
        for (int off = 16; off; off >>= 1) {
            float ov = __shfl_xor_sync(0xffffffffu, bv, off);
            int   oi = __shfl_xor_sync(0xffffffffu, bi, off);
            if (ov > bv || (ov == bv && oi < bi)) { bv = ov; bi = oi; }
        }
        // after butterfly every lane holds the global winner bi
        if (lane == 0) g_idx[bh*U_ + it] = bi;
        if (it < 32) { if (lane == it)      myrow0 = bi; }
        else         { if (lane == it - 32) myrow1 = bi; }
        // clear winning slot (global idx unique -> exactly one lane/slot)
#pragma unroll
        for (int s = 0; s < 5; s++)
            if (s == bs && ci[s] == bi) { cv[s] = -INF_F; ci[s] = 0x7fffffff; }
    }

    // fused compaction: 32 lanes register myrow0 (its 0..31),
    // lanes 0..2 also register myrow1 (its 32..34)
    if (atomicExch(&g_flag[b*L_ + myrow0], 1) == 0) {
        int p = atomicAdd(&g_cnt[b], 1);
        g_rows[b*L_ + p] = myrow0;
    }
    if (lane < U_ - 32) {
        if (atomicExch(&g_flag[b*L_ + myrow1], 1) == 0) {
            int p = atomicAdd(&g_cnt[b], 1);
            g_rows[b*L_ + p] = myrow1;
        }
    }
}

// ============================================================
__global__ __launch_bounds__(256)
void vmean_kernel()
{
    const int bh = blockIdx.x, tid = threadIdx.x;
    const int d = tid & 63, part = tid >> 6;
    const float* vp = g_v + (size_t)bh*L_*D_;
    float acc = 0.f;
    for (int l = part*256; l < part*256 + 256; l++)
        acc += vp[(size_t)l*D_ + d];
    __shared__ float red[4][64];
    red[part][d] = acc;
    __syncthreads();
    if (tid < 64)
        g_vm[bh*64 + tid] =
            (red[0][tid] + red[1][tid] + red[2][tid] + red[3][tid]) * (1.0f/L_);
}

__global__ void zero_kernel()
{
    int t = blockIdx.x*256 + threadIdx.x;
    if (t < B_*L_) g_flag[t] = 0;
    if (t < B_)    g_cnt[t]  = 0;
}

// grid (B_, 24): 16 rows per block
__global__ __launch_bounds__(256)
void x2init_kernel()
{
    const int b = blockIdx.x, t = blockIdx.y, tid = threadIdx.x;
    __shared__ float vms[F_];
    for (int f = tid; f < F_; f += 256)
        vms[f] = g_vm[(b*H_ + (f >> 6))*64 + (f & 63)];
    __syncthreads();
    const int cnt = g_cnt[b];
    int lo = t*16, hiR = lo + 16; if (hiR > cnt) hiR = cnt;
    for (int ri = lo; ri < hiR; ri++) {
        int l = g_rows[b*L_ + ri];
        float* p = g_x2 + ((size_t)b*L_ + l)*F_;
        p[tid]       = vms[tid];
        p[tid + 256] = vms[tid + 256];
    }
}

// ============================================================
__global__ __launch_bounds__(256)
void sp_scores_kernel(const int* __restrict__ mask)
{
    __shared__ float qs[U_][64];
    __shared__ float Ks[128][68];
    __shared__ int   sidx[U_];
    const int bh = blockIdx.x, tid = threadIdx.x;
    const int b = bh >> 3;
    const int kt0 = blockIdx.y << 7;
    const float* qp = g_q + (size_t)bh*L_*D_;
    const float* kp = g_k + (size_t)bh*L_*D_;
    float* scp = g_sc + (size_t)bh*U_*L_;
    const int* mrow = mask + b*L_;

    if (tid < U_) sidx[tid] = g_idx[bh*U_ + tid];
    __syncthreads();
    for (int i = tid; i < U_*16; i += 256) {
        int u = i >> 4, dc = (i & 15) << 2;
        *(float4*)&qs[u][dc] = *(const float4*)(qp + (size_t)sidx[u]*D_ + dc);
    }
    for (int i = tid; i < 128*16; i += 256) {
        int k = i >> 4, dc = (i & 15) << 2;
        *(float4*)&Ks[k][dc] = *(const float4*)(kp + (size_t)(kt0 + k)*D_ + dc);
    }
    __syncthreads();

    for (int p = tid; p < U_*128; p += 256) {
        int u = p >> 7, kk = p & 127;
        float s = 0.f;
#pragma unroll
        for (int dc = 0; dc < 64; dc += 4) {
            float4 a = *(const float4*)&qs[u][dc];
            float4 c = *(const float4*)&Ks[kk][dc];
            s += a.x*c.x + a.y*c.y + a.z*c.z + a.w*c.w;
        }
        int k = kt0 + kk;
        s *= 0.125f;
        if (mrow[k] == 0) s = -INF_F;
        scp[(size_t)u*L_ + k] = s;
    }
}

// row-parallel softmax: grid (BH_, 5), warp per selected row
__global__ __launch_bounds__(256)
void sp_softmax_kernel()
{
    const int bh = blockIdx.x, tid = threadIdx.x;
    const int wid = tid >> 5, lane = tid & 31;
    const int u = blockIdx.y * 8 + wid;
    if (u >= U_) return;
    float* scp = g_sc + (size_t)bh*U_*L_ + (size_t)u*L_;

    float mx = -INF_F;
    for (int k = lane; k < L_; k += 32)
        mx = fmaxf(mx, scp[k]);
#pragma unroll
    for (int off = 16; off; off >>= 1)
        mx = fmaxf(mx, __shfl_xor_sync(0xffffffffu, mx, off));
    float sm = 0.f;
    for (int k = lane; k < L_; k += 32) {
        float s = scp[k];
        sm += (s == -INF_F) ? 0.f : expf(s - mx);
    }
#pragma unroll
    for (int off = 16; off; off >>= 1)
        sm += __shfl_xor_sync(0xffffffffu, sm, off);
    float inv = (sm > 0.f) ? 1.0f / sm : 0.f;
    for (int k = lane; k < L_; k += 32) {
        float s = scp[k];
        float pv = (s == -INF_F || mx == -INF_F) ? 0.f : expf(s - mx) * inv;
        scp[k] = pv;
    }
}

// ============================================================
// sp_ctx split-k: grid (BH_, 4)
// ============================================================
__global__ __launch_bounds__(256)
void sp_ctx_part_kernel()
{
    __shared__ float ps[U_][64];
    __shared__ float cb[U_][64];
    const int bh = blockIdx.x, kp = blockIdx.y, tid = threadIdx.x;
    const float* vp = g_v + (size_t)bh*L_*D_;
    const float* scp = g_sc + (size_t)bh*U_*L_;
    const int d = tid & 63, part = tid >> 6;

    float acc[U_];
#pragma unroll
    for (int u = 0; u < U_; u++) acc[u] = 0.f;

    for (int kt = 0; kt < 4; kt++) {
        const int k0 = kp*256 + kt*64;
        __syncthreads();
        for (int i = tid; i < U_*64; i += 256) {
            int u = i >> 6, kk = i & 63;
            ps[u][kk] = scp[(size_t)u*L_ + k0 + kk];
        }
        __syncthreads();
        for (int kk = part*16; kk < part*16 + 16; kk++) {
            float v = vp[(size_t)(k0 + kk)*D_ + d];
#pragma unroll
            for (int u = 0; u < U_; u++)
                acc[u] += ps[u][kk] * v;
        }
    }
    __syncthreads();
    for (int p2 = 0; p2 < 4; p2++) {
        if (part == p2) {
#pragma unroll
            for (int u = 0; u < U_; u++) {
                if (p2 == 0) cb[u][d] = acc[u];
                else         cb[u][d] += acc[u];
            }
        }
        __syncthreads();
    }
    float* dst = g_ctxp + (((size_t)kp*BH_ + bh)*U_)*64;
    for (int i = tid; i < U_*64; i += 256)
        dst[i] = cb[i >> 6][i & 63];
}

__global__ __launch_bounds__(256)
void sp_scatter_kernel()
{
    __shared__ int sidx[U_];
    const int bh = blockIdx.x, tid = threadIdx.x;
    const int b = bh >> 3, h = bh & 7;
    if (tid < U_) sidx[tid] = g_idx[bh*U_ + tid];
    __syncthreads();
    float* x2 = g_x2 + (size_t)b*L_*F_ + h*D_;
    for (int i = tid; i < U_*64; i += 256) {
        int u = i >> 6, dd = i & 63;
        size_t off = (((size_t)bh)*U_ + u)*64 + dd;
        float s = g_ctxp[off]
                + g_ctxp[off + (size_t)BH_*U_*64]
                + g_ctxp[off + 2ULL*BH_*U_*64]
                + g_ctxp[off + 3ULL*BH_*U_*64];
        x2[(size_t)sidx[u]*F_ + dd] = s;
    }
}

// ============================================================
__global__ __launch_bounds__(256)
void mean_out_kernel(const float* __restrict__ Wo, const float* __restrict__ bo)
{
    const int b = blockIdx.x, t = blockIdx.y, tid = threadIdx.x;
    __shared__ float vms[F_];
    __shared__ float red[128];
    for (int f = tid; f < F_; f += 256)
        vms[f] = g_vm[(b*H_ + (f >> 6))*64 + (f & 63)];
    __syncthreads();
    const int half = tid >> 7, nloc = tid & 127;
    const int n = t*128 + nloc;
    const float* w = Wo + (size_t)n*F_ + half*256;
    const float* vv = vms + half*256;
    float s = 0.f;
#pragma unroll 8
    for (int f = 0; f < 256; f += 4) {
        float4 wv = *(const float4*)(w + f);
        s += vv[f]*wv.x + vv[f+1]*wv.y + vv[f+2]*wv.z + vv[f+3]*wv.w;
    }
    if (half) red[nloc] = s;
    __syncthreads();
    if (!half) g_om[b*F_ + n] = s + red[nloc] + bo[n];
}

__global__ __launch_bounds__(256)
void bcast_kernel(float* __restrict__ out)
{
    const int b = blockIdx.x, l0 = blockIdx.y << 3, tid = threadIdx.x;
    __shared__ float om[F_];
    for (int f = tid; f < F_; f += 256) om[f] = g_om[b*F_ + f];
    __syncthreads();
    float2 v = *(const float2*)&om[tid*2];
    float* base = out + ((size_t)b*L_ + l0)*F_;
#pragma unroll
    for (int rr = 0; rr < 8; rr++)
        *(float2*)(base + (size_t)rr*F_ + tid*2) = v;
}

// ============================================================
__global__ __launch_bounds__(256, 2)
void gemm_rows_kernel(const float* __restrict__ W,
                      const float* __restrict__ bias,
                      float* __restrict__ out)
{
    const int b = blockIdx.y / 3;
    const int t = blockIdx.y % 3;
    const int cnt = g_cnt[b];
    if (t * 128 >= cnt) return;

    __shared__ __align__(16) float As[2][16][132];
    __shared__ __align__(16) float Bs[2][16][132];
    __shared__ int rows_s[128];

    const int tid = threadIdx.x;
    if (tid < 128) {
        int gi = t*128 + tid;
        rows_s[tid] = (gi < cnt) ? g_rows[b*L_ + gi] : g_rows[b*L_];
    }
    __syncthreads();

    const float* X = g_x2 + (size_t)b*L_*F_;
    const int tx = tid & 15, ty = tid >> 4;
    const int n0 = blockIdx.x * 128;
    const int r  = tid >> 2;
    const int kc = (tid & 3) << 2;
    const int mo = r << 1;
    const int l0r = rows_s[r], l1r = rows_s[r + 64];

    u64 acc[4][8];
#pragma unroll
    for (int i = 0; i < 4; i++)
#pragma unroll
        for (int j = 0; j < 8; j++) acc[i][j] = 0ULL;

    float4 ra0, ra1, rb0, rb1;
    ra0 = *(const float4*)(X + (size_t)l0r*F_ + kc);
    ra1 = *(const float4*)(X + (size_t)l1r*F_ + kc);
    rb0 = *(const float4*)(W + (size_t)(n0 + r)*F_ + kc);
    rb1 = *(const float4*)(W + (size_t)(n0 + r + 64)*F_ + kc);

#define GSTORE(bsel) do { \
    As[bsel][kc+0][mo]   = ra0.x; As[bsel][kc+1][mo]   = ra0.y; \
    As[bsel][kc+2][mo]   = ra0.z; As[bsel][kc+3][mo]   = ra0.w; \
    As[bsel][kc+0][mo+1] = ra1.x; As[bsel][kc+1][mo+1] = ra1.y; \
    As[bsel][kc+2][mo+1] = ra1.z; As[bsel][kc+3][mo+1] = ra1.w; \
    Bs[bsel][kc+0][r]    = rb0.x; Bs[bsel][kc+1][r]    = rb0.y; \
    Bs[bsel][kc+2][r]    = rb0.z; Bs[bsel][kc+3][r]    = rb0.w; \
    Bs[bsel][kc+0][r+64] = rb1.x; Bs[bsel][kc+1][r+64] = rb1.y; \
    Bs[bsel][kc+2][r+64] = rb1.z; Bs[bsel][kc+3][r+64] = rb1.w; } while(0)

    GSTORE(0);
    __syncthreads();

    for (int c = 0; c < 32; c++) {
        if (c < 31) {
            int kb = (c + 1) << 4;
            ra0 = *(const float4*)(X + (size_t)l0r*F_ + kb + kc);
            ra1 = *(const float4*)(X + (size_t)l1r*F_ + kb + kc);
            rb0 = *(const float4*)(W + (size_t)(n0 + r)*F_ + kb + kc);
            rb1 = *(const float4*)(W + (size_t)(n0 + r + 64)*F_ + kb + kc);
        }
        const int bsel = c & 1;
#pragma unroll
        for (int kk = 0; kk < 16; kk++) {
            ulonglong2 a01 = *(const ulonglong2*)&As[bsel][kk][ty << 3];
            ulonglong2 a23 = *(const ulonglong2*)&As[bsel][kk][(ty << 3) + 4];
            float4 b0 = *(const float4*)&Bs[bsel][kk][tx << 3];
            float4 b1 = *(const float4*)&Bs[bsel][kk][(tx << 3) + 4];
            u64 av[4] = {a01.x, a01.y, a23.x, a23.y};
            u64 bv[8] = {dup2(b0.x), dup2(b0.y), dup2(b0.z), dup2(b0.w),
                         dup2(b1.x), dup2(b1.y), dup2(b1.z), dup2(b1.w)};
#pragma unroll
            for (int i = 0; i < 4; i++)
#pragma unroll
                for (int j = 0; j < 8; j++)
                    fma2(acc[i][j], av[i], bv[j]);
        }
        if (c < 31) GSTORE((c + 1) & 1);
        __syncthreads();
    }
#undef GSTORE

    const int nb = n0 + (tx << 3);
    float bb[8];
#pragma unroll
    for (int j = 0; j < 8; j++) bb[j] = bias[nb + j];

#pragma unroll
    for (int i = 0; i < 4; i++) {
        float lo[8], hi[8];
#pragma unroll
        for (int j = 0; j < 8; j++) {
            float2 tt = unpk(acc[i][j]);
            lo[j] = tt.x + bb[j];
            hi[j] = tt.y + bb[j];
        }
        {
            int l = rows_s[(ty << 2) + i];
            float* p = out + ((size_t)b*L_ + l)*F_ + nb;
            *(float4*)p     = make_float4(lo[0], lo[1], lo[2], lo[3]);
            *(float4*)(p+4) = make_float4(lo[4], lo[5], lo[6], lo[7]);
        }
        {
            int l = rows_s[(ty << 2) + i + 64];
            float* p = out + ((size_t)b*L_ + l)*F_ + nb;
            *(float4*)p     = make_float4(hi[0], hi[1], hi[2], hi[3]);
            *(float4*)(p+4) = make_float4(hi[4], hi[5], hi[6], hi[7]);
        }
    }
}

// ============================================================
extern "C" void kernel_launch(void* const* d_in, const int* in_sizes, int n_in,
                              void* d_out, int out_size)
{
    const float* query = (const float*)d_in[0];
    const float* key   = (const float*)d_in[1];
    const float* value = (const float*)d_in[2];
    const int*   mask  = (const int*)  d_in[3];
    const float* Wq = (const float*)d_in[4];
    const float* bq = (const float*)d_in[5];
    const float* Wk = (const float*)d_in[6];
    const float* bk = (const float*)d_in[7];
    const float* Wv = (const float*)d_in[8];
    const float* bv = (const float*)d_in[9];
    const float* Wo = (const float*)d_in[10];
    const float* bo = (const float*)d_in[11];
    float* out = (float*)d_out;

    float *qd, *kd, *vd;
    cudaGetSymbolAddress((void**)&qd, g_q);
    cudaGetSymbolAddress((void**)&kd, g_k);
    cudaGetSymbolAddress((void**)&vd, g_v);

    zero_kernel<<<64, 256>>>();

    hmma_proj_kernel<<<dim3(F_/128, ML_/128, 3), 256>>>(
        query, key, value, Wq, Wk, Wv, qd, kd, vd, bq, bk, bv);

    qk_hmma_kernel<<<dim3(L_/128, BH_), 256>>>();

    topk_part_kernel<<<64, 256>>>();
    topk_merge_kernel<<<16, 256>>>();
    vmean_kernel<<<BH_, 256>>>();
    x2init_kernel<<<dim3(B_, 24), 256>>>();

    sp_scores_kernel<<<dim3(BH_, 8), 256>>>(mask);
    sp_softmax_kernel<<<dim3(BH_, 5), 256>>>();
    sp_ctx_part_kernel<<<dim3(BH_, 4), 256>>>();
    sp_scatter_kernel<<<BH_, 256>>>();

    mean_out_kernel<<<dim3(B_, 4), 256>>>(Wo, bo);
    bcast_kernel<<<dim3(B_, L_/8), 256>>>(out);
    gemm_rows_kernel<<<dim3(F_/128, B_*3), 256>>>(Wo, bo, out);
}

// round 17
// speedup vs baseline: 1.3095x; 1.0889x over previous
#include <cuda_runtime.h>
#include <cuda_bf16.h>
#include <cstdint>

typedef unsigned long long u64;

#define B_  16
#define L_  1024
#define F_  512
#define H_  8
#define D_  64
#define U_  35
#define BH_ (B_*H_)
#define ML_ (B_*L_)

#define INF_F __int_as_float(0x7f800000)

// -------- device scratch --------
__device__ float g_q[(size_t)BH_*L_*D_];
__device__ float g_k[(size_t)BH_*L_*D_];
__device__ float g_v[(size_t)BH_*L_*D_];
__device__ float g_M[(size_t)BH_*L_];
__device__ int   g_idx[BH_*U_];
__device__ float g_x2[(size_t)ML_*F_];
__device__ float g_sc[(size_t)BH_*U_*L_];
__device__ float g_vm[BH_*D_];
__device__ float g_om[B_*F_];
__device__ int   g_flag[B_*L_];
__device__ int   g_cnt[B_];
__device__ int   g_rows[B_*L_];
__device__ __nv_bfloat16 g_qs[(size_t)BH_*L_*128];  // q split [hi(64)|lo(64)]
__device__ __nv_bfloat16 g_ks[(size_t)BH_*L_*128];  // k split
__device__ float g_ctxp[4ULL*BH_*U_*64];             // sp_ctx partials

// -------- helpers --------
__device__ __forceinline__ uint32_t smem_u32(const void* p) {
    uint32_t a;
    asm("{ .reg .u64 t; cvta.to.shared.u64 t, %1; cvt.u32.u64 %0, t; }" : "=r"(a) : "l"(p));
    return a;
}
#define LDSM4(r, addr) \
    asm volatile("ldmatrix.sync.aligned.m8n8.x4.shared.b16 {%0,%1,%2,%3}, [%4];" \
        : "=r"((r)[0]), "=r"((r)[1]), "=r"((r)[2]), "=r"((r)[3]) : "r"(addr))
#define MMA16816(c, a, b0v, b1v) \
    asm("mma.sync.aligned.m16n8k16.row.col.f32.bf16.bf16.f32 " \
        "{%0,%1,%2,%3}, {%4,%5,%6,%7}, {%8,%9}, {%0,%1,%2,%3};" \
        : "+f"((c)[0]), "+f"((c)[1]), "+f"((c)[2]), "+f"((c)[3]) \
        : "r"((a)[0]), "r"((a)[1]), "r"((a)[2]), "r"((a)[3]), "r"(b0v), "r"(b1v))

__device__ __forceinline__ uint32_t pack_bf2(float x, float y) {
    __nv_bfloat162 t;
    t.x = __float2bfloat16(x);
    t.y = __float2bfloat16(y);
    return *(uint32_t*)&t;
}

__device__ __forceinline__ void split8(const float* __restrict__ p,
                                       uint4 &hi, uint4 &lo) {
    float4 a = *(const float4*)p;
    float4 b = *(const float4*)(p + 4);
    float v[8] = {a.x, a.y, a.z, a.w, b.x, b.y, b.z, b.w};
    uint32_t hw[4], lw[4];
#pragma unroll
    for (int i = 0; i < 4; i++) {
        float e0 = v[2*i], e1 = v[2*i+1];
        __nv_bfloat16 h0 = __float2bfloat16(e0);
        __nv_bfloat16 h1 = __float2bfloat16(e1);
        __nv_bfloat162 hp; hp.x = h0; hp.y = h1;
        hw[i] = *(uint32_t*)&hp;
        lw[i] = pack_bf2(e0 - __bfloat162float(h0), e1 - __bfloat162float(h1));
    }
    hi = make_uint4(hw[0], hw[1], hw[2], hw[3]);
    lo = make_uint4(lw[0], lw[1], lw[2], lw[3]);
}

// term-major split MMA block (gap-4 chains)
#define MMA_GROUP(accA0, accA1, accB0, accB1, ah, al, bh, bl) do { \
    MMA16816(accA0, (ah)[0], (bh)[0], (bh)[2]); \
    MMA16816(accA1, (ah)[0], (bh)[1], (bh)[3]); \
    MMA16816(accB0, (ah)[1], (bh)[0], (bh)[2]); \
    MMA16816(accB1, (ah)[1], (bh)[1], (bh)[3]); \
    MMA16816(accA0, (ah)[0], (bl)[0], (bl)[2]); \
    MMA16816(accA1, (ah)[0], (bl)[1], (bl)[3]); \
    MMA16816(accB0, (ah)[1], (bl)[0], (bl)[2]); \
    MMA16816(accB1, (ah)[1], (bl)[1], (bl)[3]); \
    MMA16816(accA0, (al)[0], (bh)[0], (bh)[2]); \
    MMA16816(accA1, (al)[0], (bh)[1], (bh)[3]); \
    MMA16816(accB0, (al)[1], (bh)[0], (bh)[2]); \
    MMA16816(accB1, (al)[1], (bh)[1], (bh)[3]); \
} while (0)

// ============================================================
// HMMA projection GEMM with fused fp32->bf16 split loads.
// ============================================================
#define TS 72
#define TILE_E (128*TS)

__global__ __launch_bounds__(256, 2)
void hmma_proj_kernel(const float* __restrict__ xq, const float* __restrict__ xk,
                      const float* __restrict__ xv,
                      const float* __restrict__ wq, const float* __restrict__ wk,
                      const float* __restrict__ wv,
                      float* qd, float* kd, float* vd,
                      const float* __restrict__ bq,
                      const float* __restrict__ bk,
                      const float* __restrict__ bv)
{
    __shared__ __align__(16) __nv_bfloat16 Ah[TILE_E];
    __shared__ __align__(16) __nv_bfloat16 Al[TILE_E];
    __shared__ __align__(16) __nv_bfloat16 Bh[TILE_E];
    __shared__ __align__(16) __nv_bfloat16 Bl[TILE_E];

    const int tid = threadIdx.x;
    const int lane = tid & 31, wid = tid >> 5;
    const int z = blockIdx.z;
    const int m0 = blockIdx.y * 128, n0 = blockIdx.x * 128;
    const int wm = (wid >> 1) * 32;
    const int wn = (wid & 1) * 64;

    const float* X = (z == 0) ? xq : (z == 1) ? xk : xv;
    const float* W = (z == 0) ? wq : (z == 1) ? wk : wv;
    float* dst = (z == 0) ? qd : (z == 1) ? kd : vd;
    const float* bias = (z == 0) ? bq : (z == 1) ? bk : bv;

    float acc[2][8][4];
#pragma unroll
    for (int i = 0; i < 2; i++)
#pragma unroll
        for (int j = 0; j < 8; j++)
#pragma unroll
            for (int c = 0; c < 4; c++) acc[i][j][c] = 0.f;

    const int lrow = lane & 15, lhalf = lane >> 4;
    const uint32_t sAh = smem_u32(Ah), sAl = smem_u32(Al);
    const uint32_t sBh = smem_u32(Bh), sBl = smem_u32(Bl);
    uint32_t aoffH = sAh + (uint32_t)(((wm + lrow)*TS + lhalf*8) * 2);
    uint32_t aoffL = sAl + (uint32_t)(((wm + lrow)*TS + lhalf*8) * 2);
    uint32_t boffH[4], boffL[4];
#pragma unroll
    for (int nq = 0; nq < 4; nq++) {
        boffH[nq] = sBh + (uint32_t)(((wn + nq*16 + lrow)*TS + lhalf*8) * 2);
        boffL[nq] = sBl + (uint32_t)(((wn + nq*16 + lrow)*TS + lhalf*8) * 2);
    }

    const int ldrow = tid >> 3, ldc8 = (tid & 7) << 3;

    for (int kc = 0; kc < 8; kc++) {
        __syncthreads();
#pragma unroll
        for (int it = 0; it < 4; it++) {
            int row = ldrow + it*32;
            const float* xr = X + (size_t)(m0 + row)*F_ + kc*64 + ldc8;
            const float* wr = W + (size_t)(n0 + row)*F_ + kc*64 + ldc8;
            uint4 hi, lo;
            split8(xr, hi, lo);
            *(uint4*)(Ah + row*TS + ldc8) = hi;
            *(uint4*)(Al + row*TS + ldc8) = lo;
            split8(wr, hi, lo);
            *(uint4*)(Bh + row*TS + ldc8) = hi;
            *(uint4*)(Bl + row*TS + ldc8) = lo;
        }
        __syncthreads();

#pragma unroll
        for (int kt = 0; kt < 4; kt++) {
            const uint32_t kb = kt * 32;
            uint32_t ah[2][4], al[2][4];
            LDSM4(ah[0], aoffH + kb);
            LDSM4(ah[1], aoffH + kb + 16*TS*2);
            LDSM4(al[0], aoffL + kb);
            LDSM4(al[1], aoffL + kb + 16*TS*2);
#pragma unroll
            for (int nq = 0; nq < 4; nq++) {
                uint32_t bh[4], bl[4];
                LDSM4(bh, boffH[nq] + kb);
                LDSM4(bl, boffL[nq] + kb);
                MMA_GROUP(acc[0][nq*2], acc[0][nq*2+1],
                          acc[1][nq*2], acc[1][nq*2+1],
                          ah, al, bh, bl);
            }
        }
    }

    __nv_bfloat16* sp = (z == 0) ? g_qs : g_ks;
    const int r0 = lane >> 2, c0 = (lane & 3) << 1;
#pragma unroll
    for (int mi = 0; mi < 2; mi++) {
        int mA = m0 + wm + mi*16 + r0;
        int mB = mA + 8;
        int bA = mA >> 10, lA = mA & (L_-1);
        int bB = mB >> 10, lB = mB & (L_-1);
#pragma unroll
        for (int ni = 0; ni < 8; ni++) {
            int n = n0 + wn + ni*8 + c0;
            int h = n >> 6, d = n & 63;
            float b0v = bias[n], b1v = bias[n+1];
            float vA0 = acc[mi][ni][0] + b0v, vA1 = acc[mi][ni][1] + b1v;
            float vB0 = acc[mi][ni][2] + b0v, vB1 = acc[mi][ni][3] + b1v;
            size_t rowA = (size_t)(bA*H_ + h)*L_ + lA;
            size_t rowB = (size_t)(bB*H_ + h)*L_ + lB;
            *(float2*)(dst + rowA*D_ + d) = make_float2(vA0, vA1);
            *(float2*)(dst + rowB*D_ + d) = make_float2(vB0, vB1);
            if (z < 2) {
                float hA0 = __bfloat162float(__float2bfloat16(vA0));
                float hA1 = __bfloat162float(__float2bfloat16(vA1));
                float hB0 = __bfloat162float(__float2bfloat16(vB0));
                float hB1 = __bfloat162float(__float2bfloat16(vB1));
                __nv_bfloat16* pA = sp + rowA*128 + d;
                __nv_bfloat16* pB = sp + rowB*128 + d;
                *(uint32_t*)pA        = pack_bf2(vA0, vA1);
                *(uint32_t*)(pA + 64) = pack_bf2(vA0 - hA0, vA1 - hA1);
                *(uint32_t*)pB        = pack_bf2(vB0, vB1);
                *(uint32_t*)(pB + 64) = pack_bf2(vB0 - hB0, vB1 - hB1);
            }
        }
    }
}

// ============================================================
// qk M kernel via HMMA split-bf16 (static smem, 2 CTAs/SM)
// ============================================================
__global__ __launch_bounds__(256, 2)
void qk_hmma_kernel()
{
    __shared__ __align__(16) __nv_bfloat16 Qh[TILE_E];
    __shared__ __align__(16) __nv_bfloat16 Ql[TILE_E];
    __shared__ __align__(16) __nv_bfloat16 Kh[TILE_E];
    __shared__ __align__(16) __nv_bfloat16 Kl[TILE_E];
    __shared__ float redmax[2][128];
    __shared__ float redsum[2][128];

    const int tid = threadIdx.x;
    const int lane = tid & 31, wid = tid >> 5;
    const int bh_ = blockIdx.y, q0 = blockIdx.x * 128;
    const int wm = (wid >> 1) * 32, wn = (wid & 1) * 64;

    const __nv_bfloat16* qs = g_qs + (size_t)bh_*L_*128;
    const __nv_bfloat16* ks = g_ks + (size_t)bh_*L_*128;

#pragma unroll
    for (int it = 0; it < 4; it++) {
        int idx = tid + it*256;
        int row = idx >> 3, c8 = (idx & 7) << 3;
        const __nv_bfloat16* src = qs + (size_t)(q0 + row)*128 + c8;
        *(uint4*)(Qh + row*TS + c8) = *(const uint4*)(src);
        *(uint4*)(Ql + row*TS + c8) = *(const uint4*)(src + 64);
    }

    const int lrow = lane & 15, lhalf = lane >> 4;
    const uint32_t sQh = smem_u32(Qh), sQl = smem_u32(Ql);
    const uint32_t sKh = smem_u32(Kh), sKl = smem_u32(Kl);
    uint32_t aoffH = sQh + (uint32_t)(((wm + lrow)*TS + lhalf*8) * 2);
    uint32_t aoffL = sQl + (uint32_t)(((wm + lrow)*TS + lhalf*8) * 2);
    uint32_t boffH[4], boffL[4];
#pragma unroll
    for (int nq = 0; nq < 4; nq++) {
        boffH[nq] = sKh + (uint32_t)(((wn + nq*16 + lrow)*TS + lhalf*8) * 2);
        boffL[nq] = sKl + (uint32_t)(((wn + nq*16 + lrow)*TS + lhalf*8) * 2);
    }

    float rmax_[2][2], rsum_[2][2];
#pragma unroll
    for (int i = 0; i < 2; i++)
#pragma unroll
        for (int j = 0; j < 2; j++) { rmax_[i][j] = -INF_F; rsum_[i][j] = 0.f; }

    for (int kt = 0; kt < 8; kt++) {
        __syncthreads();
#pragma unroll
        for (int it = 0; it < 4; it++) {
            int idx = tid + it*256;
            int row = idx >> 3, c8 = (idx & 7) << 3;
            const __nv_bfloat16* src = ks + (size_t)(kt*128 + row)*128 + c8;
            *(uint4*)(Kh + row*TS + c8) = *(const uint4*)(src);
            *(uint4*)(Kl + row*TS + c8) = *(const uint4*)(src + 64);
        }
        __syncthreads();

        float acc[2][8][4];
#pragma unroll
        for (int i = 0; i < 2; i++)
#pragma unroll
            for (int j = 0; j < 8; j++)
#pragma unroll
                for (int c = 0; c < 4; c++) acc[i][j][c] = 0.f;

#pragma unroll
        for (int k16 = 0; k16 < 4; k16++) {
            const uint32_t kb = k16 * 32;
            uint32_t ah[2][4], al[2][4];
            LDSM4(ah[0], aoffH + kb);
            LDSM4(ah[1], aoffH + kb + 16*TS*2);
            LDSM4(al[0], aoffL + kb);
            LDSM4(al[1], aoffL + kb + 16*TS*2);
#pragma unroll
            for (int nq = 0; nq < 4; nq++) {
                uint32_t bhf[4], blf[4];
                LDSM4(bhf, boffH[nq] + kb);
                LDSM4(blf, boffL[nq] + kb);
                MMA_GROUP(acc[0][nq*2], acc[0][nq*2+1],
                          acc[1][nq*2], acc[1][nq*2+1],
                          ah, al, bhf, blf);
            }
        }

#pragma unroll
        for (int mi = 0; mi < 2; mi++) {
            float m0 = -INF_F, m1 = -INF_F, s0 = 0.f, s1 = 0.f;
#pragma unroll
            for (int ni = 0; ni < 8; ni++) {
                m0 = fmaxf(m0, fmaxf(acc[mi][ni][0], acc[mi][ni][1]));
                s0 += acc[mi][ni][0] + acc[mi][ni][1];
                m1 = fmaxf(m1, fmaxf(acc[mi][ni][2], acc[mi][ni][3]));
                s1 += acc[mi][ni][2] + acc[mi][ni][3];
            }
            rmax_[mi][0] = fmaxf(rmax_[mi][0], m0); rsum_[mi][0] += s0;
            rmax_[mi][1] = fmaxf(rmax_[mi][1], m1); rsum_[mi][1] += s1;
        }
    }

#pragma unroll
    for (int mi = 0; mi < 2; mi++)
#pragma unroll
        for (int hf = 0; hf < 2; hf++) {
            float m = rmax_[mi][hf], s = rsum_[mi][hf];
#pragma unroll
            for (int off = 1; off <= 2; off <<= 1) {
                m = fmaxf(m, __shfl_xor_sync(0xffffffffu, m, off));
                s += __shfl_xor_sync(0xffffffffu, s, off);
            }
            rmax_[mi][hf] = m; rsum_[mi][hf] = s;
        }
    if ((lane & 3) == 0) {
        int r0 = lane >> 2;
#pragma unroll
        for (int mi = 0; mi < 2; mi++)
#pragma unroll
            for (int hf = 0; hf < 2; hf++) {
                int row = wm + mi*16 + hf*8 + r0;
                redmax[wid & 1][row] = rmax_[mi][hf];
                redsum[wid & 1][row] = rsum_[mi][hf];
            }
    }
    __syncthreads();
    if (tid < 128) {
        float m = fmaxf(redmax[0][tid], redmax[1][tid]);
        float s = redsum[0][tid] + redsum[1][tid];
        g_M[(size_t)bh_*L_ + q0 + tid] = m - s * (1.0f/L_);
    }
}

// ============================================================
// single-kernel top-35: block per bh (128 thr = 4 warps).
// Warp w: top-35 of quarter w -> smem candidates.
// Warp 0: merge 140 -> g_idx + fused compaction.
// ============================================================
__global__ __launch_bounds__(128)
void topk_kernel()
{
    __shared__ float scv[4*U_];
    __shared__ int   sci[4*U_];
    const int warp = threadIdx.x >> 5, lane = threadIdx.x & 31;
    const int bh = blockIdx.x, b = bh >> 3;

    // phase 1: quarter top-35
    {
        const float* Mp = g_M + (size_t)bh*L_ + warp*256;
        float v[8];
#pragma unroll
        for (int j = 0; j < 8; j++) v[j] = Mp[j*32 + lane];
        for (int it = 0; it < U_; it++) {
            float bv = v[0]; int bj = 0;
#pragma unroll
            for (int j = 1; j < 8; j++)
                if (v[j] > bv) { bv = v[j]; bj = j; }
            int bk = warp*256 + bj*32 + lane;
#pragma unroll
            for (int off = 16; off; off >>= 1) {
                float ov = __shfl_xor_sync(0xffffffffu, bv, off);
                int   ok = __shfl_xor_sync(0xffffffffu, bk, off);
                if (ov > bv || (ov == bv && ok < bk)) { bv = ov; bk = ok; }
            }
            if (lane == 0) { scv[warp*U_ + it] = bv; sci[warp*U_ + it] = bk; }
            int lk = bk - warp*256;
            int cj = lk >> 5;
            bool mine = ((lk & 31) == lane);
#pragma unroll
            for (int j = 0; j < 8; j++)
                if (mine && j == cj) v[j] = -INF_F;
        }
    }
    __syncthreads();

    // phase 2: warp 0 merges 140 candidates
    if (warp == 0) {
        float cv[5]; int ci[5];
#pragma unroll
        for (int s = 0; s < 5; s++) {
            int c = lane + s*32;
            bool ok = (c < 4*U_);
            cv[s] = ok ? scv[c] : -INF_F;
            ci[s] = ok ? sci[c] : 0x7fffffff;
        }
        int myrow0 = -1, myrow1 = -1;
        for (int it = 0; it < U_; it++) {
            float bv = cv[0]; int bi = ci[0], bs = 0;
#pragma unroll
            for (int s = 1; s < 5; s++)
                if (cv[s] > bv || (cv[s] == bv && ci[s] < bi)) {
                    bv = cv[s]; bi = ci[s]; bs = s;
                }
#pragma unroll
            for (int off = 16; off; off >>= 1) {
                float ov = __shfl_xor_sync(0xffffffffu, bv, off);
                int   oi = __shfl_xor_sync(0xffffffffu, bi, off);
                if (ov > bv || (ov == bv && oi < bi)) { bv = ov; bi = oi; }
            }
            if (lane == 0) g_idx[bh*U_ + it] = bi;
            if (it < 32) { if (lane == it)      myrow0 = bi; }
            else         { if (lane == it - 32) myrow1 = bi; }
#pragma unroll
            for (int s = 0; s < 5; s++)
                if (s == bs && ci[s] == bi) { cv[s] = -INF_F; ci[s] = 0x7fffffff; }
        }
        if (atomicExch(&g_flag[b*L_ + myrow0], 1) == 0) {
            int p = atomicAdd(&g_cnt[b], 1);
            g_rows[b*L_ + p] = myrow0;
        }
        if (lane < U_ - 32) {
            if (atomicExch(&g_flag[b*L_ + myrow1], 1) == 0) {
                int p = atomicAdd(&g_cnt[b], 1);
                g_rows[b*L_ + p] = myrow1;
            }
        }
    }
}

// ============================================================
__global__ __launch_bounds__(256)
void vmean_kernel()
{
    const int bh = blockIdx.x, tid = threadIdx.x;
    const int d = tid & 63, part = tid >> 6;
    const float* vp = g_v + (size_t)bh*L_*D_;
    float acc = 0.f;
    for (int l = part*256; l < part*256 + 256; l++)
        acc += vp[(size_t)l*D_ + d];
    __shared__ float red[4][64];
    red[part][d] = acc;
    __syncthreads();
    if (tid < 64)
        g_vm[bh*64 + tid] =
            (red[0][tid] + red[1][tid] + red[2][tid] + red[3][tid]) * (1.0f/L_);
}

__global__ void zero_kernel()
{
    int t = blockIdx.x*256 + threadIdx.x;
    if (t < B_*L_) g_flag[t] = 0;
    if (t < B_)    g_cnt[t]  = 0;
}

// grid (B_, 24): 16 rows per block
__global__ __launch_bounds__(256)
void x2init_kernel()
{
    const int b = blockIdx.x, t = blockIdx.y, tid = threadIdx.x;
    __shared__ float vms[F_];
    for (int f = tid; f < F_; f += 256)
        vms[f] = g_vm[(b*H_ + (f >> 6))*64 + (f & 63)];
    __syncthreads();
    const int cnt = g_cnt[b];
    int lo = t*16, hiR = lo + 16; if (hiR > cnt) hiR = cnt;
    for (int ri = lo; ri < hiR; ri++) {
        int l = g_rows[b*L_ + ri];
        float* p = g_x2 + ((size_t)b*L_ + l)*F_;
        p[tid]       = vms[tid];
        p[tid + 256] = vms[tid + 256];
    }
}

// ============================================================
__global__ __launch_bounds__(256)
void sp_scores_kernel(const int* __restrict__ mask)
{
    __shared__ float qs[U_][64];
    __shared__ float Ks[128][68];
    __shared__ int   sidx[U_];
    const int bh = blockIdx.x, tid = threadIdx.x;
    const int b = bh >> 3;
    const int kt0 = blockIdx.y << 7;
    const float* qp = g_q + (size_t)bh*L_*D_;
    const float* kp = g_k + (size_t)bh*L_*D_;
    float* scp = g_sc + (size_t)bh*U_*L_;
    const int* mrow = mask + b*L_;

    if (tid < U_) sidx[tid] = g_idx[bh*U_ + tid];
    __syncthreads();
    for (int i = tid; i < U_*16; i += 256) {
        int u = i >> 4, dc = (i & 15) << 2;
        *(float4*)&qs[u][dc] = *(const float4*)(qp + (size_t)sidx[u]*D_ + dc);
    }
    for (int i = tid; i < 128*16; i += 256) {
        int k = i >> 4, dc = (i & 15) << 2;
        *(float4*)&Ks[k][dc] = *(const float4*)(kp + (size_t)(kt0 + k)*D_ + dc);
    }
    __syncthreads();

    for (int p = tid; p < U_*128; p += 256) {
        int u = p >> 7, kk = p & 127;
        float s = 0.f;
#pragma unroll
        for (int dc = 0; dc < 64; dc += 4) {
            float4 a = *(const float4*)&qs[u][dc];
            float4 c = *(const float4*)&Ks[kk][dc];
            s += a.x*c.x + a.y*c.y + a.z*c.z + a.w*c.w;
        }
        int k = kt0 + kk;
        s *= 0.125f;
        if (mrow[k] == 0) s = -INF_F;
        scp[(size_t)u*L_ + k] = s;
    }
}

// row-parallel softmax: grid (BH_, 5), warp per selected row
__global__ __launch_bounds__(256)
void sp_softmax_kernel()
{
    const int bh = blockIdx.x, tid = threadIdx.x;
    const int wid = tid >> 5, lane = tid & 31;
    const int u = blockIdx.y * 8 + wid;
    if (u >= U_) return;
    float* scp = g_sc + (size_t)bh*U_*L_ + (size_t)u*L_;

    float mx = -INF_F;
    for (int k = lane; k < L_; k += 32)
        mx = fmaxf(mx, scp[k]);
#pragma unroll
    for (int off = 16; off; off >>= 1)
        mx = fmaxf(mx, __shfl_xor_sync(0xffffffffu, mx, off));
    float sm = 0.f;
    for (int k = lane; k < L_; k += 32) {
        float s = scp[k];
        sm += (s == -INF_F) ? 0.f : expf(s - mx);
    }
#pragma unroll
    for (int off = 16; off; off >>= 1)
        sm += __shfl_xor_sync(0xffffffffu, sm, off);
    float inv = (sm > 0.f) ? 1.0f / sm : 0.f;
    for (int k = lane; k < L_; k += 32) {
        float s = scp[k];
        float pv = (s == -INF_F || mx == -INF_F) ? 0.f : expf(s - mx) * inv;
        scp[k] = pv;
    }
}

// ============================================================
// sp_ctx split-k: grid (BH_, 4)
// ============================================================
__global__ __launch_bounds__(256)
void sp_ctx_part_kernel()
{
    __shared__ float ps[U_][64];
    __shared__ float cb[U_][64];
    const int bh = blockIdx.x, kp = blockIdx.y, tid = threadIdx.x;
    const float* vp = g_v + (size_t)bh*L_*D_;
    const float* scp = g_sc + (size_t)bh*U_*L_;
    const int d = tid & 63, part = tid >> 6;

    float acc[U_];
#pragma unroll
    for (int u = 0; u < U_; u++) acc[u] = 0.f;

    for (int kt = 0; kt < 4; kt++) {
        const int k0 = kp*256 + kt*64;
        __syncthreads();
        for (int i = tid; i < U_*64; i += 256) {
            int u = i >> 6, kk = i & 63;
            ps[u][kk] = scp[(size_t)u*L_ + k0 + kk];
        }
        __syncthreads();
        for (int kk = part*16; kk < part*16 + 16; kk++) {
            float v = vp[(size_t)(k0 + kk)*D_ + d];
#pragma unroll
            for (int u = 0; u < U_; u++)
                acc[u] += ps[u][kk] * v;
        }
    }
    __syncthreads();
    for (int p2 = 0; p2 < 4; p2++) {
        if (part == p2) {
#pragma unroll
            for (int u = 0; u < U_; u++) {
                if (p2 == 0) cb[u][d] = acc[u];
                else         cb[u][d] += acc[u];
            }
        }
        __syncthreads();
    }
    float* dst = g_ctxp + (((size_t)kp*BH_ + bh)*U_)*64;
    for (int i = tid; i < U_*64; i += 256)
        dst[i] = cb[i >> 6][i & 63];
}

__global__ __launch_bounds__(256)
void sp_scatter_kernel()
{
    __shared__ int sidx[U_];
    const int bh = blockIdx.x, tid = threadIdx.x;
    const int b = bh >> 3, h = bh & 7;
    if (tid < U_) sidx[tid] = g_idx[bh*U_ + tid];
    __syncthreads();
    float* x2 = g_x2 + (size_t)b*L_*F_ + h*D_;
    for (int i = tid; i < U_*64; i += 256) {
        int u = i >> 6, dd = i & 63;
        size_t off = (((size_t)bh)*U_ + u)*64 + dd;
        float s = g_ctxp[off]
                + g_ctxp[off + (size_t)BH_*U_*64]
                + g_ctxp[off + 2ULL*BH_*U_*64]
                + g_ctxp[off + 3ULL*BH_*U_*64];
        x2[(size_t)sidx[u]*F_ + dd] = s;
    }
}

// ============================================================
__global__ __launch_bounds__(256)
void mean_out_kernel(const float* __restrict__ Wo, const float* __restrict__ bo)
{
    const int b = blockIdx.x, t = blockIdx.y, tid = threadIdx.x;
    __shared__ float vms[F_];
    __shared__ float red[128];
    for (int f = tid; f < F_; f += 256)
        vms[f] = g_vm[(b*H_ + (f >> 6))*64 + (f & 63)];
    __syncthreads();
    const int half = tid >> 7, nloc = tid & 127;
    const int n = t*128 + nloc;
    const float* w = Wo + (size_t)n*F_ + half*256;
    const float* vv = vms + half*256;
    float s = 0.f;
#pragma unroll 8
    for (int f = 0; f < 256; f += 4) {
        float4 wv = *(const float4*)(w + f);
        s += vv[f]*wv.x + vv[f+1]*wv.y + vv[f+2]*wv.z + vv[f+3]*wv.w;
    }
    if (half) red[nloc] = s;
    __syncthreads();
    if (!half) g_om[b*F_ + n] = s + red[nloc] + bo[n];
}

__global__ __launch_bounds__(256)
void bcast_kernel(float* __restrict__ out)
{
    const int b = blockIdx.x, l0 = blockIdx.y << 3, tid = threadIdx.x;
    __shared__ float om[F_];
    for (int f = tid; f < F_; f += 256) om[f] = g_om[b*F_ + f];
    __syncthreads();
    float2 v = *(const float2*)&om[tid*2];
    float* base = out + ((size_t)b*L_ + l0)*F_;
#pragma unroll
    for (int rr = 0; rr < 8; rr++)
        *(float2*)(base + (size_t)rr*F_ + tid*2) = v;
}

// ============================================================
// output GEMM over compacted rows: HMMA split-bf16 with fused
// split loads (A gathered via rows_s). grid (4, B_*3).
// ============================================================
__global__ __launch_bounds__(256, 2)
void hmma_rows_kernel(const float* __restrict__ Wo,
                      const float* __restrict__ bo,
                      float* __restrict__ out)
{
    __shared__ __align__(16) __nv_bfloat16 Ah[TILE_E];
    __shared__ __align__(16) __nv_bfloat16 Al[TILE_E];
    __shared__ __align__(16) __nv_bfloat16 Bh[TILE_E];
    __shared__ __align__(16) __nv_bfloat16 Bl[TILE_E];
    __shared__ int rows_s[128];

    const int tid = threadIdx.x;
    const int lane = tid & 31, wid = tid >> 5;
    const int b = blockIdx.y / 3, t = blockIdx.y % 3;
    const int cnt = g_cnt[b];
    if (t*128 >= cnt) return;
    const int n0 = blockIdx.x * 128;
    const int wm = (wid >> 1) * 32;
    const int wn = (wid & 1) * 64;

    if (tid < 128) {
        int gi = t*128 + tid;
        rows_s[tid] = (gi < cnt) ? g_rows[b*L_ + gi] : g_rows[b*L_];
    }
    __syncthreads();

    const float* X = g_x2 + (size_t)b*L_*F_;

    float acc[2][8][4];
#pragma unroll
    for (int i = 0; i < 2; i++)
#pragma unroll
        for (int j = 0; j < 8; j++)
#pragma unroll
            for (int c = 0; c < 4; c++) acc[i][j][c] = 0.f;

    const int lrow = lane & 15, lhalf = lane >> 4;
    const uint32_t sAh = smem_u32(Ah), sAl = smem_u32(Al);
    const uint32_t sBh = smem_u32(Bh), sBl = smem_u32(Bl);
    uint32_t aoffH = sAh + (uint32_t)(((wm + lrow)*TS + lhalf*8) * 2);
    uint32_t aoffL = sAl + (uint32_t)(((wm + lrow)*TS + lhalf*8) * 2);
    uint32_t boffH[4], boffL[4];
#pragma unroll
    for (int nq = 0; nq < 4; nq++) {
        boffH[nq] = sBh + (uint32_t)(((wn + nq*16 + lrow)*TS + lhalf*8) * 2);
        boffL[nq] = sBl + (uint32_t)(((wn + nq*16 + lrow)*TS + lhalf*8) * 2);
    }

    const int ldrow = tid >> 3, ldc8 = (tid & 7) << 3;

    for (int kc = 0; kc < 8; kc++) {
        __syncthreads();
#pragma unroll
        for (int it = 0; it < 4; it++) {
            int row = ldrow + it*32;
            int l = rows_s[row];
            const float* xr = X + (size_t)l*F_ + kc*64 + ldc8;
            const float* wr = Wo + (size_t)(n0 + row)*F_ + kc*64 + ldc8;
            uint4 hi, lo;
            split8(xr, hi, lo);
            *(uint4*)(Ah + row*TS + ldc8) = hi;
            *(uint4*)(Al + row*TS + ldc8) = lo;
            split8(wr, hi, lo);
            *(uint4*)(Bh + row*TS + ldc8) = hi;
            *(uint4*)(Bl + row*TS + ldc8) = lo;
        }
        __syncthreads();

#pragma unroll
        for (int kt = 0; kt < 4; kt++) {
            const uint32_t kb = kt * 32;
            uint32_t ah[2][4], al[2][4];
            LDSM4(ah[0], aoffH + kb);
            LDSM4(ah[1], aoffH + kb + 16*TS*2);
            LDSM4(al[0], aoffL + kb);
            LDSM4(al[1], aoffL + kb + 16*TS*2);
#pragma unroll
            for (int nq = 0; nq < 4; nq++) {
                uint32_t bh[4], bl[4];
                LDSM4(bh, boffH[nq] + kb);
                LDSM4(bl, boffL[nq] + kb);
                MMA_GROUP(acc[0][nq*2], acc[0][nq*2+1],
                          acc[1][nq*2], acc[1][nq*2+1],
                          ah, al, bh, bl);
            }
        }
    }

    const int r0 = lane >> 2, c0 = (lane & 3) << 1;
#pragma unroll
    for (int mi = 0; mi < 2; mi++) {
        int trA = wm + mi*16 + r0;
        int trB = trA + 8;
        int lA = rows_s[trA], lB = rows_s[trB];
        bool okA = (t*128 + trA) < cnt;
        bool okB = (t*128 + trB) < cnt;
#pragma unroll
        for (int ni = 0; ni < 8; ni++) {
            int n = n0 + wn + ni*8 + c0;
            float b0v = bo[n], b1v = bo[n+1];
            if (okA)
                *(float2*)(out + ((size_t)b*L_ + lA)*F_ + n) =
                    make_float2(acc[mi][ni][0] + b0v, acc[mi][ni][1] + b1v);
            if (okB)
                *(float2*)(out + ((size_t)b*L_ + lB)*F_ + n) =
                    make_float2(acc[mi][ni][2] + b0v, acc[mi][ni][3] + b1v);
        }
    }
}

// ============================================================
extern "C" void kernel_launch(void* const* d_in, const int* in_sizes, int n_in,
                              void* d_out, int out_size)
{
    const float* query = (const float*)d_in[0];
    const float* key   = (const float*)d_in[1];
    const float* value = (const float*)d_in[2];
    const int*   mask  = (const int*)  d_in[3];
    const float* Wq = (const float*)d_in[4];
    const float* bq = (const float*)d_in[5];
    const float* Wk = (const float*)d_in[6];
    const float* bk = (const float*)d_in[7];
    const float* Wv = (const float*)d_in[8];
    const float* bv = (const float*)d_in[9];
    const float* Wo = (const float*)d_in[10];
    const float* bo = (const float*)d_in[11];
    float* out = (float*)d_out;

    float *qd, *kd, *vd;
    cudaGetSymbolAddress((void**)&qd, g_q);
    cudaGetSymbolAddress((void**)&kd, g_k);
    cudaGetSymbolAddress((void**)&vd, g_v);

    zero_kernel<<<64, 256>>>();

    hmma_proj_kernel<<<dim3(F_/128, ML_/128, 3), 256>>>(
        query, key, value, Wq, Wk, Wv, qd, kd, vd, bq, bk, bv);

    qk_hmma_kernel<<<dim3(L_/128, BH_), 256>>>();

    topk_kernel<<<BH_, 128>>>();
    vmean_kernel<<<BH_, 256>>>();
    x2init_kernel<<<dim3(B_, 24), 256>>>();

    sp_scores_kernel<<<dim3(BH_, 8), 256>>>(mask);
    sp_softmax_kernel<<<dim3(BH_, 5), 256>>>();
    sp_ctx_part_kernel<<<dim3(BH_, 4), 256>>>();
    sp_scatter_kernel<<<BH_, 256>>>();

    mean_out_kernel<<<dim3(B_, 4), 256>>>(Wo, bo);
    bcast_kernel<<<dim3(B_, L_/8), 256>>>(out);
    hmma_rows_kernel<<<dim3(F_/128, B_*3), 256>>>(Wo, bo, out);
}